// round 15
// baseline (speedup 1.0000x reference)
#include <cuda_runtime.h>
#include <cuda_fp16.h>

#define NN 50000
#define EE 100000

// word offsets in dynamic smem
#define OFF_WQ  640
#define OFF_WO  (OFF_WQ + 192*36)
#define OFF_W1  (OFF_WO + 64*36)
#define OFF_W2  (OFF_W1 + 64*36)
#define OFF_ACT (OFF_W2 + 64*36)     // 14464
// per-sub, 2 edges (words): xch 0(2x576) aoh 1152(2x576) qvh 2304(2x1088)
//   vpw 4480(2x768) xcf 6016(2x1088 f32) pp 8192(2x128 f32)
#define SUBW 8448
#define SMEM_WORDS (OFF_ACT + 4*SUBW)

__device__ float  g_hA[(size_t)NN * 512];
__device__ float  g_hB[(size_t)NN * 512];
__device__ __half g_hCh[(size_t)NN * 512];   // bproj(h) per node, fp16
__device__ float  g_inv[NN];
__device__ int    g_any;

__global__ void setup0_kernel() {
    size_t i = (size_t)blockIdx.x * blockDim.x + threadIdx.x;
    if (i == 0) g_any = 0;
    if (i < NN) g_inv[i] = 0.f;
    if (i < (size_t)NN * 128) ((float4*)g_hB)[i] = make_float4(0.f, 0.f, 0.f, 0.f);
}
__global__ void detect_kernel(const int* __restrict__ ei) {
    int i = blockIdx.x * blockDim.x + threadIdx.x;
    int v = 0;
    for (int k = i; k < EE; k += gridDim.x * blockDim.x) v |= ei[2 * k + 1];
    if (v) atomicOr(&g_any, 1);
}
__global__ void embed_kernel(const float* __restrict__ x, const float* __restrict__ nw,
                             const float* __restrict__ nb) {
    int i = blockIdx.x * blockDim.x + threadIdx.x;
    if (i < NN * 512) {
        int n = i >> 9, r = i & 511;
        g_hA[i] = x[n * 8 + (r >> 6)] * nw[r] + nb[r];
    }
}
__global__ void count_kernel(const int* __restrict__ ei) {
    int e = blockIdx.x * blockDim.x + threadIdx.x;
    if (e < EE) {
        int t = (g_any == 0) ? ei[2 * (EE + e)] : ei[EE + e];
        atomicAdd(&g_inv[t], 1.0f);
    }
}
__global__ void fin_cnt_kernel() {
    int i = blockIdx.x * blockDim.x + threadIdx.x;
    if (i < NN) g_inv[i] = 1.0f / fmaxf(g_inv[i], 1.0f);
}
__global__ void zeroA_kernel() {
    size_t i = (size_t)blockIdx.x * blockDim.x + threadIdx.x;
    if (i < (size_t)NN * 128) ((float4*)g_hA)[i] = make_float4(0.f, 0.f, 0.f, 0.f);
}

// ---- f16 mma helpers ----
__device__ __forceinline__ void mma_f16(float& c0, float& c1, float& c2, float& c3,
                                        unsigned a0, unsigned a1, unsigned a2, unsigned a3,
                                        unsigned b0, unsigned b1) {
    asm volatile(
        "mma.sync.aligned.m16n8k16.row.col.f32.f16.f16.f32 "
        "{%0,%1,%2,%3}, {%4,%5,%6,%7}, {%8,%9}, {%0,%1,%2,%3};\n"
        : "+f"(c0), "+f"(c1), "+f"(c2), "+f"(c3)
        : "r"(a0), "r"(a1), "r"(a2), "r"(a3), "r"(b0), "r"(b1));
}
__device__ __forceinline__ unsigned packh2(float hi, float lo) {
    unsigned d;
    asm("cvt.rn.f16x2.f32 %0, %1, %2;" : "=r"(d) : "f"(hi), "f"(lo));
    return d;
}
__device__ __forceinline__ void load_ah(unsigned a[4][4], const unsigned* __restrict__ X,
                                        int lane) {
    int row = lane >> 2, tg = lane & 3;
    const unsigned* p0 = X + row * 36 + tg;
    const unsigned* p1 = X + (row + 8) * 36 + tg;
    #pragma unroll
    for (int kc = 0; kc < 4; kc++) {
        a[kc][0] = p0[kc * 8];
        a[kc][1] = p1[kc * 8];
        a[kc][2] = p0[kc * 8 + 4];
        a[kc][3] = p1[kc * 8 + 4];
    }
}

// ---- per-node bproj pre-pass: g_hCh = half( h @ bpw^T + bpb ) ----
// input buffer selected by `which` INSIDE device code (device symbols must
// never be passed from host).
__global__ void __launch_bounds__(128, 4)
bproj_kernel(int which, const float* __restrict__ bpw, const float* __restrict__ bpb) {
    __shared__ unsigned wsh[64 * 36];
    __shared__ float sbias[64];
    __shared__ unsigned ash[16 * 36];
    const float* hin = which ? g_hB : g_hA;
    int tid = threadIdx.x;
    __half* wh = (__half*)wsh;
    for (int i = tid; i < 64 * 64; i += 128)
        wh[(i >> 6) * 72 + (i & 63)] = __float2half_rn(bpw[i]);
    if (tid < 64) sbias[tid] = bpb[tid];
    __syncthreads();
    int warp = tid >> 5, lane = tid & 31;
    int g = lane >> 2, tg = lane & 3;
    const int NT = (NN * 8) / 16;   // 25000 tiles of 16 token-rows
    for (int t = blockIdx.x; t < NT; t += gridDim.x) {
        const float* src = hin + (size_t)t * 1024;
        {
            int row = tid >> 3, c8 = (tid & 7) * 8;
            float4 u0 = *(const float4*)(src + row * 64 + c8);
            float4 u1 = *(const float4*)(src + row * 64 + c8 + 4);
            int wb = row * 36 + (c8 >> 1);
            ash[wb]     = packh2(u0.y, u0.x);
            ash[wb + 1] = packh2(u0.w, u0.z);
            ash[wb + 2] = packh2(u1.y, u1.x);
            ash[wb + 3] = packh2(u1.w, u1.z);
        }
        __syncthreads();
        unsigned a[4][4];
        load_ah(a, ash, lane);
        unsigned* dstw = (unsigned*)(g_hCh + (size_t)t * 1024);
        #pragma unroll
        for (int jt = 0; jt < 2; jt++) {
            int jb = warp * 16 + jt * 8;
            int col0 = jb + 2 * tg;
            float2 bb = *(const float2*)(sbias + col0);
            float c0 = bb.x, c1 = bb.y, c2 = bb.x, c3 = bb.y;
            const unsigned* wr = wsh + (jb + g) * 36 + tg;
            #pragma unroll
            for (int kc = 0; kc < 4; kc++)
                mma_f16(c0, c1, c2, c3, a[kc][0], a[kc][1], a[kc][2], a[kc][3],
                        wr[kc * 8], wr[kc * 8 + 4]);
            dstw[g * 32 + (col0 >> 1)]       = packh2(c1, c0);
            dstw[(g + 8) * 32 + (col0 >> 1)] = packh2(c3, c2);
        }
        __syncthreads();
    }
}

// two-edge tile: one B load, two 4-MMA chains.
template<int EPI, bool ROWS8, bool HOUT, bool FOUT>
__device__ __forceinline__ void gemm2(const unsigned a0[4][4], const unsigned a1[4][4],
                                      const unsigned* __restrict__ W,
                                      const float* __restrict__ bias, int jbase,
                                      unsigned* Ch0, unsigned* Ch1, int chw,
                                      float* Cf0, float* Cf1, int cfw,
                                      const float* R0, const float* R1, int rw, int lane) {
    int g = lane >> 2, tg = lane & 3;
    int col0 = jbase + 2 * tg;
    float2 bb = *(const float2*)(bias + col0);
    float d00 = bb.x, d01 = bb.y, d02 = bb.x, d03 = bb.y;
    float d10 = bb.x, d11 = bb.y, d12 = bb.x, d13 = bb.y;
    const unsigned* wr = W + (jbase + g) * 36 + tg;
    unsigned b0[4], b1[4];
    #pragma unroll
    for (int kc = 0; kc < 4; kc++) { b0[kc] = wr[kc * 8]; b1[kc] = wr[kc * 8 + 4]; }
    #pragma unroll
    for (int kc = 0; kc < 4; kc++)
        mma_f16(d00, d01, d02, d03, a0[kc][0], a0[kc][1], a0[kc][2], a0[kc][3], b0[kc], b1[kc]);
    #pragma unroll
    for (int kc = 0; kc < 4; kc++)
        mma_f16(d10, d11, d12, d13, a1[kc][0], a1[kc][1], a1[kc][2], a1[kc][3], b0[kc], b1[kc]);
    if (EPI == 2) {
        float2 r00 = *(const float2*)(R0 + g * rw + col0);
        float2 r01 = *(const float2*)(R0 + (g + 8) * rw + col0);
        float2 r10 = *(const float2*)(R1 + g * rw + col0);
        float2 r11 = *(const float2*)(R1 + (g + 8) * rw + col0);
        d00 += r00.x; d01 += r00.y; d02 += r01.x; d03 += r01.y;
        d10 += r10.x; d11 += r10.y; d12 += r11.x; d13 += r11.y;
    }
    if (EPI == 1) {
        d00 = fmaxf(d00, 0.f); d01 = fmaxf(d01, 0.f); d02 = fmaxf(d02, 0.f); d03 = fmaxf(d03, 0.f);
        d10 = fmaxf(d10, 0.f); d11 = fmaxf(d11, 0.f); d12 = fmaxf(d12, 0.f); d13 = fmaxf(d13, 0.f);
    }
    if (HOUT) {
        Ch0[g * chw + (jbase >> 1) + tg] = packh2(d01, d00);
        Ch1[g * chw + (jbase >> 1) + tg] = packh2(d11, d10);
        if (!ROWS8) {
            Ch0[(g + 8) * chw + (jbase >> 1) + tg] = packh2(d03, d02);
            Ch1[(g + 8) * chw + (jbase >> 1) + tg] = packh2(d13, d12);
        }
    }
    if (FOUT) {
        *(float2*)(Cf0 + g * cfw + col0) = make_float2(d00, d01);
        *(float2*)(Cf1 + g * cfw + col0) = make_float2(d10, d11);
        if (!ROWS8) {
            *(float2*)(Cf0 + (g + 8) * cfw + col0) = make_float2(d02, d03);
            *(float2*)(Cf1 + (g + 8) * cfw + col0) = make_float2(d12, d13);
        }
    }
}

#define SUBBAR() asm volatile("bar.sync %0, 128;" :: "r"(sub + 1) : "memory")
#define XCH(e) (subw + (e)*576)
#define AOH(e) (subw + 1152 + (e)*576)
#define QVH(e) (subw + 2304 + (e)*1088)
#define VPW(e) (subw + 4480 + (e)*768)
#define XCF(e) ((float*)(subw + 6016 + (e)*1088))
#define PP(e)  ((float*)(subw + 8192 + (e)*128))

__global__ void __launch_bounds__(512, 1)
edge_kernel(const int* __restrict__ ei, int dir,
            const float* __restrict__ ipw, const float* __restrict__ ipb,
            const float* __restrict__ opw, const float* __restrict__ opb,
            const float* __restrict__ ln1g, const float* __restrict__ ln1b,
            const float* __restrict__ ln2g, const float* __restrict__ ln2b,
            const float* __restrict__ w1,  const float* __restrict__ fb1,
            const float* __restrict__ w2,  const float* __restrict__ fb2) {
    extern __shared__ float sm[];
    unsigned* smw = (unsigned*)sm;
    float* s_b = sm;
    __half* whq = (__half*)(smw + OFF_WQ);
    __half* who = (__half*)(smw + OFF_WO);
    __half* wh1 = (__half*)(smw + OFF_W1);
    __half* wh2 = (__half*)(smw + OFF_W2);

    const float* hin  = dir ? g_hB : g_hA;
    float*       hout = dir ? g_hA : g_hB;
    const int tid = threadIdx.x;

    for (int i = tid; i < 192 * 64; i += 512)
        whq[(i >> 6) * 72 + (i & 63)] = __float2half_rn(ipw[i]);
    for (int i = tid; i < 64 * 64; i += 512) {
        int r = (i >> 6) * 72 + (i & 63);
        who[r] = __float2half_rn(opw[i]);
        wh1[r] = __float2half_rn(w1[i]);
        wh2[r] = __float2half_rn(w2[i]);
    }
    for (int i = tid; i < 192; i += 512) s_b[i] = ipb[i];
    if (tid < 64) {
        s_b[192 + tid] = opb[tid];  s_b[256 + tid] = fb1[tid];
        s_b[320 + tid] = fb2[tid];  s_b[384 + tid] = ln1g[tid];
        s_b[448 + tid] = ln1b[tid]; s_b[512 + tid] = ln2g[tid];
        s_b[576 + tid] = ln2b[tid];
    }
    __syncthreads();

    const int sub  = tid >> 7;
    const int st   = tid & 127;
    const int warp = st >> 5;
    const int lane = st & 31;
    const int g    = lane >> 2, tg = lane & 3;
    unsigned* subw = smw + OFF_ACT + sub * SUBW;

    const unsigned* Wq  = smw + OFF_WQ;
    const unsigned* Wo  = smw + OFF_WO;
    const unsigned* W1p = smw + OFF_W1;
    const unsigned* W2p = smw + OFF_W2;

    const int is64 = (g_any == 0);
    const int r0 = st >> 4, d0 = (st & 15) << 2;
    const int stride8 = gridDim.x * 8;

    // prologue prefetch (2 edges): tgt row f32 from hin, bproj'd src row fp16 from g_hCh
    bool pv0, pv1; int pt0 = 0, pt1 = 0; float pc0 = 0.f, pc1 = 0.f;
    float4 pvi0 = make_float4(0,0,0,0), pvi1 = pvi0;
    uint2 pj0 = make_uint2(0, 0), pj1 = pj0;
    {
        int e0 = blockIdx.x * 8 + sub * 2;
        pv0 = e0 < EE; pv1 = (e0 + 1) < EE;
        if (pv0) {
            int s0 = is64 ? ei[2 * e0] : ei[e0];
            pt0    = is64 ? ei[2 * (EE + e0)] : ei[EE + e0];
            pc0 = g_inv[pt0];
            pvi0 = *(const float4*)(hin + (size_t)pt0 * 512 + r0 * 64 + d0);
            pj0  = *(const uint2*)(g_hCh + (size_t)s0 * 512 + r0 * 64 + d0);
        }
        if (pv1) {
            int e1 = e0 + 1;
            int s1 = is64 ? ei[2 * e1] : ei[e1];
            pt1    = is64 ? ei[2 * (EE + e1)] : ei[EE + e1];
            pc1 = g_inv[pt1];
            pvi1 = *(const float4*)(hin + (size_t)pt1 * 512 + r0 * 64 + d0);
            pj1  = *(const uint2*)(g_hCh + (size_t)s1 * 512 + r0 * 64 + d0);
        }
    }

    for (int base = blockIdx.x * 8; base < EE; base += stride8) {
        const bool v0 = pv0, v1 = pv1;
        const int  t0i = pt0, t1i = pt1;
        const float c0i = pc0, c1i = pc1;

        // P0: commit gathers (rows 0..7 = tgt f32+half; rows 8..15 = bproj'd src half + f32 copy)
        if (v0) {
            *(float4*)(XCF(0) + r0 * 68 + d0) = pvi0;
            int wb = r0 * 36 + (d0 >> 1), wb2 = (8 + r0) * 36 + (d0 >> 1);
            XCH(0)[wb]      = packh2(pvi0.y, pvi0.x);
            XCH(0)[wb + 1]  = packh2(pvi0.w, pvi0.z);
            XCH(0)[wb2]     = pj0.x;
            XCH(0)[wb2 + 1] = pj0.y;
            float2 f0 = __half22float2(*(__half2*)&pj0.x);
            float2 f1 = __half22float2(*(__half2*)&pj0.y);
            *(float4*)(XCF(0) + (8 + r0) * 68 + d0) = make_float4(f0.x, f0.y, f1.x, f1.y);
        }
        if (v1) {
            *(float4*)(XCF(1) + r0 * 68 + d0) = pvi1;
            int wb = r0 * 36 + (d0 >> 1), wb2 = (8 + r0) * 36 + (d0 >> 1);
            XCH(1)[wb]      = packh2(pvi1.y, pvi1.x);
            XCH(1)[wb + 1]  = packh2(pvi1.w, pvi1.z);
            XCH(1)[wb2]     = pj1.x;
            XCH(1)[wb2 + 1] = pj1.y;
            float2 f0 = __half22float2(*(__half2*)&pj1.x);
            float2 f1 = __half22float2(*(__half2*)&pj1.y);
            *(float4*)(XCF(1) + (8 + r0) * 68 + d0) = make_float4(f0.x, f0.y, f1.x, f1.y);
        }
        SUBBAR();

        // prefetch next iteration
        {
            int e0 = base + stride8 + sub * 2;
            pv0 = e0 < EE; pv1 = (e0 + 1) < EE;
            if (pv0) {
                int s0 = is64 ? ei[2 * e0] : ei[e0];
                pt0    = is64 ? ei[2 * (EE + e0)] : ei[EE + e0];
                pc0 = g_inv[pt0];
                pvi0 = *(const float4*)(hin + (size_t)pt0 * 512 + r0 * 64 + d0);
                pj0  = *(const uint2*)(g_hCh + (size_t)s0 * 512 + r0 * 64 + d0);
            }
            if (pv1) {
                int e1 = e0 + 1;
                int s1 = is64 ? ei[2 * e1] : ei[e1];
                pt1    = is64 ? ei[2 * (EE + e1)] : ei[EE + e1];
                pc1 = g_inv[pt1];
                pvi1 = *(const float4*)(hin + (size_t)pt1 * 512 + r0 * 64 + d0);
                pj1  = *(const uint2*)(g_hCh + (size_t)s1 * 512 + r0 * 64 + d0);
            }
        }

        // P2+P3 fused: warp computes ITS OWN head's q/k/v, then its attention.
        if (v0) {
            unsigned a0[4][4], a1[4][4];
            load_ah(a0, XCH(0), lane);
            load_ah(a1, XCH(1), lane);
            #pragma unroll
            for (int nt = 0; nt < 6; nt++) {
                int jb = (nt < 2) ? (warp * 16 + nt * 8)
                       : (nt < 4) ? (64 + warp * 16 + (nt - 2) * 8)
                                  : (128 + warp * 16 + (nt - 4) * 8);
                int col0 = jb + 2 * tg;
                float2 bb = *(const float2*)(s_b + col0);
                float d00 = bb.x, d01 = bb.y, d02 = bb.x, d03 = bb.y;
                float d10 = bb.x, d11 = bb.y, d12 = bb.x, d13 = bb.y;
                const unsigned* wr = Wq + (jb + g) * 36 + tg;
                unsigned b0[4], b1[4];
                #pragma unroll
                for (int kc = 0; kc < 4; kc++) { b0[kc] = wr[kc * 8]; b1[kc] = wr[kc * 8 + 4]; }
                #pragma unroll
                for (int kc = 0; kc < 4; kc++)
                    mma_f16(d00, d01, d02, d03, a0[kc][0], a0[kc][1], a0[kc][2], a0[kc][3], b0[kc], b1[kc]);
                #pragma unroll
                for (int kc = 0; kc < 4; kc++)
                    mma_f16(d10, d11, d12, d13, a1[kc][0], a1[kc][1], a1[kc][2], a1[kc][3], b0[kc], b1[kc]);
                if (jb < 128) {
                    QVH(0)[g * 68 + (jb >> 1) + tg]       = packh2(d01, d00);
                    QVH(0)[(g + 8) * 68 + (jb >> 1) + tg] = packh2(d03, d02);
                    QVH(1)[g * 68 + (jb >> 1) + tg]       = packh2(d11, d10);
                    QVH(1)[(g + 8) * 68 + (jb >> 1) + tg] = packh2(d13, d12);
                } else {
                    int dL = jb - 128 + 2 * tg;
                    __half* vp0 = (__half*)VPW(0);
                    __half* vp1 = (__half*)VPW(1);
                    vp0[dL * 24 + g]           = __float2half_rn(d00);
                    vp0[(dL + 1) * 24 + g]     = __float2half_rn(d01);
                    vp0[dL * 24 + g + 8]       = __float2half_rn(d02);
                    vp0[(dL + 1) * 24 + g + 8] = __float2half_rn(d03);
                    vp1[dL * 24 + g]           = __float2half_rn(d10);
                    vp1[(dL + 1) * 24 + g]     = __float2half_rn(d11);
                    vp1[dL * 24 + g + 8]       = __float2half_rn(d12);
                    vp1[(dL + 1) * 24 + g + 8] = __float2half_rn(d13);
                }
            }
            __syncwarp();

            // P3: attention for head `warp` (both edges), P in registers
            #pragma unroll
            for (int e = 0; e < 2; e++) {
                const unsigned* qb = QVH(e) + warp * 8;
                const unsigned* kb = QVH(e) + 32 + warp * 8;
                unsigned a0q = qb[g * 68 + tg],     a1q = qb[(g + 8) * 68 + tg];
                unsigned a2q = qb[g * 68 + tg + 4], a3q = qb[(g + 8) * 68 + tg + 4];
                float s00 = 0, s01 = 0, s02 = 0, s03 = 0;
                float s10 = 0, s11 = 0, s12 = 0, s13 = 0;
                mma_f16(s00, s01, s02, s03, a0q, a1q, a2q, a3q,
                        kb[g * 68 + tg], kb[g * 68 + tg + 4]);
                mma_f16(s10, s11, s12, s13, a0q, a1q, a2q, a3q,
                        kb[(g + 8) * 68 + tg], kb[(g + 8) * 68 + tg + 4]);
                s00 *= 0.25f; s01 *= 0.25f; s02 *= 0.25f; s03 *= 0.25f;
                s10 *= 0.25f; s11 *= 0.25f; s12 *= 0.25f; s13 *= 0.25f;
                float m0 = fmaxf(fmaxf(s00, s01), fmaxf(s10, s11));
                float m1 = fmaxf(fmaxf(s02, s03), fmaxf(s12, s13));
                m0 = fmaxf(m0, __shfl_xor_sync(0xffffffffu, m0, 1));
                m0 = fmaxf(m0, __shfl_xor_sync(0xffffffffu, m0, 2));
                m1 = fmaxf(m1, __shfl_xor_sync(0xffffffffu, m1, 1));
                m1 = fmaxf(m1, __shfl_xor_sync(0xffffffffu, m1, 2));
                float e00 = __expf(s00 - m0), e01 = __expf(s01 - m0);
                float e10 = __expf(s10 - m0), e11 = __expf(s11 - m0);
                float e02 = __expf(s02 - m1), e03 = __expf(s03 - m1);
                float e12 = __expf(s12 - m1), e13 = __expf(s13 - m1);
                float t0 = (e00 + e01) + (e10 + e11);
                float t1 = (e02 + e03) + (e12 + e13);
                t0 += __shfl_xor_sync(0xffffffffu, t0, 1);
                t0 += __shfl_xor_sync(0xffffffffu, t0, 2);
                t1 += __shfl_xor_sync(0xffffffffu, t1, 1);
                t1 += __shfl_xor_sync(0xffffffffu, t1, 2);
                float r0s = 1.f / t0, r1s = 1.f / t1;
                unsigned ap0 = packh2(e01 * r0s, e00 * r0s);
                unsigned ap1 = packh2(e03 * r1s, e02 * r1s);
                unsigned ap2 = packh2(e11 * r0s, e10 * r0s);
                unsigned ap3 = packh2(e13 * r1s, e12 * r1s);
                const unsigned* vb = VPW(e) + warp * 192;
                unsigned* ao = AOH(e);
                #pragma unroll
                for (int jb2 = 0; jb2 < 2; jb2++) {
                    float c0 = 0, c1 = 0, c2 = 0, c3 = 0;
                    const unsigned* vr = vb + (jb2 * 8 + g) * 12 + tg;
                    mma_f16(c0, c1, c2, c3, ap0, ap1, ap2, ap3, vr[0], vr[4]);
                    ao[g * 36 + warp * 8 + jb2 * 4 + tg]       = packh2(c1, c0);
                    ao[(g + 8) * 36 + warp * 8 + jb2 * 4 + tg] = packh2(c3, c2);
                }
            }
        }
        SUBBAR();

        // P4: out_proj + residual, register-resident; emit LN1 partials
        float p4[2][8];
        if (v0) {
            unsigned a0[4][4], a1[4][4];
            load_ah(a0, AOH(0), lane);
            load_ah(a1, AOH(1), lane);
            #pragma unroll
            for (int jt = 0; jt < 2; jt++) {
                int jb = warp * 16 + jt * 8;
                int col0 = jb + 2 * tg;
                float2 bb = *(const float2*)(s_b + 192 + col0);
                float d00 = bb.x, d01 = bb.y, d02 = bb.x, d03 = bb.y;
                float d10 = bb.x, d11 = bb.y, d12 = bb.x, d13 = bb.y;
                const unsigned* wr = Wo + (jb + g) * 36 + tg;
                unsigned b0[4], b1[4];
                #pragma unroll
                for (int kc = 0; kc < 4; kc++) { b0[kc] = wr[kc * 8]; b1[kc] = wr[kc * 8 + 4]; }
                #pragma unroll
                for (int kc = 0; kc < 4; kc++)
                    mma_f16(d00, d01, d02, d03, a0[kc][0], a0[kc][1], a0[kc][2], a0[kc][3], b0[kc], b1[kc]);
                #pragma unroll
                for (int kc = 0; kc < 4; kc++)
                    mma_f16(d10, d11, d12, d13, a1[kc][0], a1[kc][1], a1[kc][2], a1[kc][3], b0[kc], b1[kc]);
                float2 r00 = *(const float2*)(XCF(0) + g * 68 + col0);
                float2 r01 = *(const float2*)(XCF(0) + (g + 8) * 68 + col0);
                float2 r10 = *(const float2*)(XCF(1) + g * 68 + col0);
                float2 r11 = *(const float2*)(XCF(1) + (g + 8) * 68 + col0);
                p4[0][jt * 4 + 0] = d00 + r00.x; p4[0][jt * 4 + 1] = d01 + r00.y;
                p4[0][jt * 4 + 2] = d02 + r01.x; p4[0][jt * 4 + 3] = d03 + r01.y;
                p4[1][jt * 4 + 0] = d10 + r10.x; p4[1][jt * 4 + 1] = d11 + r10.y;
                p4[1][jt * 4 + 2] = d12 + r11.x; p4[1][jt * 4 + 3] = d13 + r11.y;
            }
            #pragma unroll
            for (int e = 0; e < 2; e++) {
                float sg  = (p4[e][0] + p4[e][1]) + (p4[e][4] + p4[e][5]);
                float sg8 = (p4[e][2] + p4[e][3]) + (p4[e][6] + p4[e][7]);
                float qg  = p4[e][0]*p4[e][0] + p4[e][1]*p4[e][1] + p4[e][4]*p4[e][4] + p4[e][5]*p4[e][5];
                float qg8 = p4[e][2]*p4[e][2] + p4[e][3]*p4[e][3] + p4[e][6]*p4[e][6] + p4[e][7]*p4[e][7];
                sg  += __shfl_xor_sync(0xffffffffu, sg, 1);  sg  += __shfl_xor_sync(0xffffffffu, sg, 2);
                sg8 += __shfl_xor_sync(0xffffffffu, sg8, 1); sg8 += __shfl_xor_sync(0xffffffffu, sg8, 2);
                qg  += __shfl_xor_sync(0xffffffffu, qg, 1);  qg  += __shfl_xor_sync(0xffffffffu, qg, 2);
                qg8 += __shfl_xor_sync(0xffffffffu, qg8, 1); qg8 += __shfl_xor_sync(0xffffffffu, qg8, 2);
                if (tg == 0) {
                    float* ppe = PP(e);
                    ppe[g * 8 + warp]           = sg;
                    ppe[g * 8 + 4 + warp]       = qg;
                    ppe[(g + 8) * 8 + warp]     = sg8;
                    ppe[(g + 8) * 8 + 4 + warp] = qg8;
                }
            }
        }
        SUBBAR();

        // LN1 finish: combine partials, normalize registers, write XCF(rows0-7) + XCH
        if (v0) {
            #pragma unroll
            for (int e = 0; e < 2; e++) {
                float* ppe = PP(e);
                float4 sx  = *(const float4*)(ppe + g * 8);
                float4 sq  = *(const float4*)(ppe + g * 8 + 4);
                float4 sx8 = *(const float4*)(ppe + (g + 8) * 8);
                float4 sq8 = *(const float4*)(ppe + (g + 8) * 8 + 4);
                float mu   = ((sx.x + sx.y) + (sx.z + sx.w)) * 0.015625f;
                float ex2  = ((sq.x + sq.y) + (sq.z + sq.w)) * 0.015625f;
                float mu8  = ((sx8.x + sx8.y) + (sx8.z + sx8.w)) * 0.015625f;
                float ex28 = ((sq8.x + sq8.y) + (sq8.z + sq8.w)) * 0.015625f;
                float rstd  = rsqrtf(ex2 - mu * mu + 1e-5f);
                float rstd8 = rsqrtf(ex28 - mu8 * mu8 + 1e-5f);
                #pragma unroll
                for (int jt = 0; jt < 2; jt++) {
                    int jb = warp * 16 + jt * 8;
                    int col0 = jb + 2 * tg;
                    float2 gg = *(const float2*)(s_b + 384 + col0);
                    float2 be = *(const float2*)(s_b + 448 + col0);
                    float o0 = (p4[e][jt * 4 + 0] - mu) * rstd * gg.x + be.x;
                    float o1 = (p4[e][jt * 4 + 1] - mu) * rstd * gg.y + be.y;
                    float o2 = (p4[e][jt * 4 + 2] - mu8) * rstd8 * gg.x + be.x;
                    float o3 = (p4[e][jt * 4 + 3] - mu8) * rstd8 * gg.y + be.y;
                    *(float2*)(XCF(e) + g * 68 + col0) = make_float2(o0, o1);
                    XCH(e)[g * 36 + (jb >> 1) + tg]       = packh2(o1, o0);
                    XCH(e)[(g + 8) * 36 + (jb >> 1) + tg] = packh2(o3, o2);
                }
            }
        }
        SUBBAR();

        // P6: FF1 + relu -> AOH
        if (v0) {
            unsigned a0[4][4], a1[4][4];
            load_ah(a0, XCH(0), lane);
            load_ah(a1, XCH(1), lane);
            gemm2<1, false, true, false>(a0, a1, W1p, s_b + 256, warp * 16,
                AOH(0), AOH(1), 36, 0, 0, 0, 0, 0, 0, lane);
            gemm2<1, false, true, false>(a0, a1, W1p, s_b + 256, warp * 16 + 8,
                AOH(0), AOH(1), 36, 0, 0, 0, 0, 0, 0, lane);
        }
        SUBBAR();

        // P7: FF2 + residual (rows 0..7 only), register-resident; LN2 partials
        float p7[2][4];
        if (v0) {
            unsigned a0[4][4], a1[4][4];
            load_ah(a0, AOH(0), lane);
            load_ah(a1, AOH(1), lane);
            #pragma unroll
            for (int jt = 0; jt < 2; jt++) {
                int jb = warp * 16 + jt * 8;
                int col0 = jb + 2 * tg;
                float2 bb = *(const float2*)(s_b + 320 + col0);
                float d00 = bb.x, d01 = bb.y, d02 = bb.x, d03 = bb.y;
                float d10 = bb.x, d11 = bb.y, d12 = bb.x, d13 = bb.y;
                const unsigned* wr = W2p + (jb + g) * 36 + tg;
                unsigned b0[4], b1[4];
                #pragma unroll
                for (int kc = 0; kc < 4; kc++) { b0[kc] = wr[kc * 8]; b1[kc] = wr[kc * 8 + 4]; }
                #pragma unroll
                for (int kc = 0; kc < 4; kc++)
                    mma_f16(d00, d01, d02, d03, a0[kc][0], a0[kc][1], a0[kc][2], a0[kc][3], b0[kc], b1[kc]);
                #pragma unroll
                for (int kc = 0; kc < 4; kc++)
                    mma_f16(d10, d11, d12, d13, a1[kc][0], a1[kc][1], a1[kc][2], a1[kc][3], b0[kc], b1[kc]);
                float2 r0v = *(const float2*)(XCF(0) + g * 68 + col0);
                float2 r1v = *(const float2*)(XCF(1) + g * 68 + col0);
                p7[0][jt * 2 + 0] = d00 + r0v.x; p7[0][jt * 2 + 1] = d01 + r0v.y;
                p7[1][jt * 2 + 0] = d10 + r1v.x; p7[1][jt * 2 + 1] = d11 + r1v.y;
            }
            #pragma unroll
            for (int e = 0; e < 2; e++) {
                float sg = (p7[e][0] + p7[e][1]) + (p7[e][2] + p7[e][3]);
                float qg = p7[e][0]*p7[e][0] + p7[e][1]*p7[e][1] + p7[e][2]*p7[e][2] + p7[e][3]*p7[e][3];
                sg += __shfl_xor_sync(0xffffffffu, sg, 1); sg += __shfl_xor_sync(0xffffffffu, sg, 2);
                qg += __shfl_xor_sync(0xffffffffu, qg, 1); qg += __shfl_xor_sync(0xffffffffu, qg, 2);
                if (tg == 0) {
                    float* ppe = PP(e);
                    ppe[g * 8 + warp]     = sg;
                    ppe[g * 8 + 4 + warp] = qg;
                }
            }
        }
        SUBBAR();

        // LN2 finish + scaled vector-atomic scatter (rows 0..7)
        #pragma unroll
        for (int e = 0; e < 2; e++) {
            bool ve = e ? v1 : v0;
            if (!ve) continue;
            int tgte = e ? t1i : t0i;
            float ice = e ? c1i : c0i;
            float* ppe = PP(e);
            float4 sx = *(const float4*)(ppe + g * 8);
            float4 sq = *(const float4*)(ppe + g * 8 + 4);
            float mu  = ((sx.x + sx.y) + (sx.z + sx.w)) * 0.015625f;
            float ex2 = ((sq.x + sq.y) + (sq.z + sq.w)) * 0.015625f;
            float rstd = rsqrtf(ex2 - mu * mu + 1e-5f);
            #pragma unroll
            for (int jt = 0; jt < 2; jt++) {
                int col0 = warp * 16 + jt * 8 + 2 * tg;
                float2 gg = *(const float2*)(s_b + 512 + col0);
                float2 be = *(const float2*)(s_b + 576 + col0);
                float o0 = ((p7[e][jt * 2 + 0] - mu) * rstd * gg.x + be.x) * ice;
                float o1 = ((p7[e][jt * 2 + 1] - mu) * rstd * gg.y + be.y) * ice;
                float* dst = hout + (size_t)tgte * 512 + g * 64 + col0;
                asm volatile("red.global.add.v2.f32 [%0], {%1,%2};"
                             :: "l"(dst), "f"(o0), "f"(o1) : "memory");
            }
        }
        // no trailing barrier: LN2 reads PP (next written at P4, barriers away);
        // next P0 writes XCH/XCF, last read at P7 (behind a barrier).
    }
}

__global__ void out_kernel(const float* __restrict__ ow, const float* __restrict__ ob,
                           float* __restrict__ out) {
    __shared__ float shs[8][64];
    int w = threadIdx.x >> 5, lane = threadIdx.x & 31;
    int n = blockIdx.x * 8 + w;
    if (n >= NN) return;
    const float* hr = g_hA + (size_t)n * 512;
    float lo = 0.f, hi = 0.f;
    #pragma unroll
    for (int c = 0; c < 8; c++) { lo += hr[c * 64 + lane]; hi += hr[c * 64 + 32 + lane]; }
    shs[w][lane] = lo; shs[w][lane + 32] = hi;
    __syncwarp();
    float z = -1e30f;
    if (lane < 16) {
        float acc = 8.f * ob[lane];
        const float* wr = ow + lane * 64;
        #pragma unroll
        for (int d = 0; d < 64; d++) acc = fmaf(shs[w][d], wr[d], acc);
        z = acc;
    }
    float m = z;
    #pragma unroll
    for (int off = 8; off; off >>= 1) m = fmaxf(m, __shfl_xor_sync(0xffffffffu, m, off, 16));
    float p = __expf(z - m);
    float s = p;
    #pragma unroll
    for (int off = 8; off; off >>= 1) s += __shfl_xor_sync(0xffffffffu, s, off, 16);
    if (lane < 16) out[n * 16 + lane] = p / s;
}

extern "C" void kernel_launch(void* const* d_in, const int* in_sizes, int n_in,
                              void* d_out, int out_size) {
    const float* x    = (const float*)d_in[0];
    const int*   ei   = (const int*)d_in[1];
    const float* numw = (const float*)d_in[2];
    const float* numb = (const float*)d_in[3];
    const float* bpw  = (const float*)d_in[4];
    const float* bpb  = (const float*)d_in[5];
    const float* ipw  = (const float*)d_in[6];
    const float* ipb  = (const float*)d_in[7];
    const float* opw  = (const float*)d_in[8];
    const float* opb  = (const float*)d_in[9];
    const float* g1   = (const float*)d_in[10];
    const float* b1   = (const float*)d_in[11];
    const float* g2   = (const float*)d_in[12];
    const float* b2   = (const float*)d_in[13];
    const float* w1   = (const float*)d_in[14];
    const float* fb1  = (const float*)d_in[15];
    const float* w2   = (const float*)d_in[16];
    const float* fb2  = (const float*)d_in[17];
    const float* ow   = (const float*)d_in[18];
    const float* ob   = (const float*)d_in[19];
    float* out = (float*)d_out;

    const int SMEM_BYTES = SMEM_WORDS * 4;
    cudaFuncSetAttribute(edge_kernel, cudaFuncAttributeMaxDynamicSharedMemorySize, SMEM_BYTES);

    int dev = 0, sms = 148;
    cudaGetDevice(&dev);
    cudaDeviceGetAttribute(&sms, cudaDevAttrMultiProcessorCount, dev);

    setup0_kernel<<<(NN * 128 + 255) / 256, 256>>>();
    detect_kernel<<<256, 256>>>(ei);
    embed_kernel<<<(NN * 512 + 255) / 256, 256>>>(x, numw, numb);
    count_kernel<<<(EE + 255) / 256, 256>>>(ei);
    fin_cnt_kernel<<<(NN + 255) / 256, 256>>>();

    // layer 0: hA -> hB
    bproj_kernel<<<sms * 8, 128>>>(0, bpw, bpb);
    edge_kernel<<<sms, 512, SMEM_BYTES>>>(ei, 0,
        ipw, ipb, opw, opb, g1, b1, g2, b2, w1, fb1, w2, fb2);

    // layer 1: hB -> hA
    zeroA_kernel<<<(NN * 128 + 255) / 256, 256>>>();
    bproj_kernel<<<sms * 8, 128>>>(1, bpw + 64 * 64, bpb + 64);
    edge_kernel<<<sms, 512, SMEM_BYTES>>>(ei, 1,
        ipw + 192 * 64, ipb + 192, opw + 64 * 64, opb + 64,
        g1 + 64, b1 + 64, g2 + 64, b2 + 64,
        w1 + 64 * 64, fb1 + 64, w2 + 64 * 64, fb2 + 64);

    out_kernel<<<(NN + 7) / 8, 256>>>(ow, ob, out);
}

// round 16
// speedup vs baseline: 1.0016x; 1.0016x over previous
#include <cuda_runtime.h>
#include <cuda_fp16.h>

#define NN 50000
#define EE 100000

// word offsets in dynamic smem
#define OFF_WQ  704
#define OFF_WO  (OFF_WQ + 192*36)
#define OFF_W1  (OFF_WO + 64*36)
#define OFF_W2  (OFF_W1 + 64*36)
#define OFF_WB  (OFF_W2 + 64*36)
#define OFF_ACT (OFF_WB + 64*36)     // 16832
// per-sub, 2 edges (words): xsh 0(2x288) xch 576(2x576) aoh 1728(2x576)
//   qvh 2880(2x1088) vpw 5056(2x768) xcf 6592(2x1088 f32) pp 8768(2x128 f32)
#define SUBW 9024
#define SMEM_WORDS (OFF_ACT + 4*SUBW)

__device__ float g_hA[(size_t)NN * 512];
__device__ float g_hB[(size_t)NN * 512];
__device__ float g_inv[NN];
__device__ int   g_any;

__global__ void setup0_kernel() {
    size_t i = (size_t)blockIdx.x * blockDim.x + threadIdx.x;
    if (i == 0) g_any = 0;
    if (i < NN) g_inv[i] = 0.f;
    if (i < (size_t)NN * 128) ((float4*)g_hB)[i] = make_float4(0.f, 0.f, 0.f, 0.f);
}
__global__ void detect_kernel(const int* __restrict__ ei) {
    int i = blockIdx.x * blockDim.x + threadIdx.x;
    int v = 0;
    for (int k = i; k < EE; k += gridDim.x * blockDim.x) v |= ei[2 * k + 1];
    if (v) atomicOr(&g_any, 1);
}
__global__ void embed_kernel(const float* __restrict__ x, const float* __restrict__ nw,
                             const float* __restrict__ nb) {
    int i = blockIdx.x * blockDim.x + threadIdx.x;
    if (i < NN * 512) {
        int n = i >> 9, r = i & 511;
        g_hA[i] = x[n * 8 + (r >> 6)] * nw[r] + nb[r];
    }
}
__global__ void count_kernel(const int* __restrict__ ei) {
    int e = blockIdx.x * blockDim.x + threadIdx.x;
    if (e < EE) {
        int t = (g_any == 0) ? ei[2 * (EE + e)] : ei[EE + e];
        atomicAdd(&g_inv[t], 1.0f);
    }
}
__global__ void fin_cnt_kernel() {
    int i = blockIdx.x * blockDim.x + threadIdx.x;
    if (i < NN) g_inv[i] = 1.0f / fmaxf(g_inv[i], 1.0f);
}
__global__ void zeroA_kernel() {
    size_t i = (size_t)blockIdx.x * blockDim.x + threadIdx.x;
    if (i < (size_t)NN * 128) ((float4*)g_hA)[i] = make_float4(0.f, 0.f, 0.f, 0.f);
}

// ---- f16 mma helpers ----
__device__ __forceinline__ void mma_f16(float& c0, float& c1, float& c2, float& c3,
                                        unsigned a0, unsigned a1, unsigned a2, unsigned a3,
                                        unsigned b0, unsigned b1) {
    asm volatile(
        "mma.sync.aligned.m16n8k16.row.col.f32.f16.f16.f32 "
        "{%0,%1,%2,%3}, {%4,%5,%6,%7}, {%8,%9}, {%0,%1,%2,%3};\n"
        : "+f"(c0), "+f"(c1), "+f"(c2), "+f"(c3)
        : "r"(a0), "r"(a1), "r"(a2), "r"(a3), "r"(b0), "r"(b1));
}
__device__ __forceinline__ unsigned packh2(float hi, float lo) {
    unsigned d;
    asm("cvt.rn.f16x2.f32 %0, %1, %2;" : "=r"(d) : "f"(hi), "f"(lo));
    return d;
}
__device__ __forceinline__ void load_ah(unsigned a[4][4], const unsigned* __restrict__ X,
                                        int lane) {
    int row = lane >> 2, tg = lane & 3;
    const unsigned* p0 = X + row * 36 + tg;
    const unsigned* p1 = X + (row + 8) * 36 + tg;
    #pragma unroll
    for (int kc = 0; kc < 4; kc++) {
        a[kc][0] = p0[kc * 8];
        a[kc][1] = p1[kc * 8];
        a[kc][2] = p0[kc * 8 + 4];
        a[kc][3] = p1[kc * 8 + 4];
    }
}

// two-edge tile: one B load, two 4-MMA chains.
template<int EPI, bool ROWS8, bool HOUT, bool FOUT>
__device__ __forceinline__ void gemm2(const unsigned a0[4][4], const unsigned a1[4][4],
                                      const unsigned* __restrict__ W,
                                      const float* __restrict__ bias, int jbase,
                                      unsigned* Ch0, unsigned* Ch1, int chw,
                                      float* Cf0, float* Cf1, int cfw,
                                      const float* R0, const float* R1, int rw, int lane) {
    int g = lane >> 2, tg = lane & 3;
    int col0 = jbase + 2 * tg;
    float2 bb = *(const float2*)(bias + col0);
    float d00 = bb.x, d01 = bb.y, d02 = bb.x, d03 = bb.y;
    float d10 = bb.x, d11 = bb.y, d12 = bb.x, d13 = bb.y;
    const unsigned* wr = W + (jbase + g) * 36 + tg;
    unsigned b0[4], b1[4];
    #pragma unroll
    for (int kc = 0; kc < 4; kc++) { b0[kc] = wr[kc * 8]; b1[kc] = wr[kc * 8 + 4]; }
    #pragma unroll
    for (int kc = 0; kc < 4; kc++)
        mma_f16(d00, d01, d02, d03, a0[kc][0], a0[kc][1], a0[kc][2], a0[kc][3], b0[kc], b1[kc]);
    #pragma unroll
    for (int kc = 0; kc < 4; kc++)
        mma_f16(d10, d11, d12, d13, a1[kc][0], a1[kc][1], a1[kc][2], a1[kc][3], b0[kc], b1[kc]);
    if (EPI == 2) {
        float2 r00 = *(const float2*)(R0 + g * rw + col0);
        float2 r01 = *(const float2*)(R0 + (g + 8) * rw + col0);
        float2 r10 = *(const float2*)(R1 + g * rw + col0);
        float2 r11 = *(const float2*)(R1 + (g + 8) * rw + col0);
        d00 += r00.x; d01 += r00.y; d02 += r01.x; d03 += r01.y;
        d10 += r10.x; d11 += r10.y; d12 += r11.x; d13 += r11.y;
    }
    if (EPI == 1) {
        d00 = fmaxf(d00, 0.f); d01 = fmaxf(d01, 0.f); d02 = fmaxf(d02, 0.f); d03 = fmaxf(d03, 0.f);
        d10 = fmaxf(d10, 0.f); d11 = fmaxf(d11, 0.f); d12 = fmaxf(d12, 0.f); d13 = fmaxf(d13, 0.f);
    }
    if (HOUT) {
        Ch0[g * chw + (jbase >> 1) + tg] = packh2(d01, d00);
        Ch1[g * chw + (jbase >> 1) + tg] = packh2(d11, d10);
        if (!ROWS8) {
            Ch0[(g + 8) * chw + (jbase >> 1) + tg] = packh2(d03, d02);
            Ch1[(g + 8) * chw + (jbase >> 1) + tg] = packh2(d13, d12);
        }
    }
    if (FOUT) {
        *(float2*)(Cf0 + g * cfw + col0) = make_float2(d00, d01);
        *(float2*)(Cf1 + g * cfw + col0) = make_float2(d10, d11);
        if (!ROWS8) {
            *(float2*)(Cf0 + (g + 8) * cfw + col0) = make_float2(d02, d03);
            *(float2*)(Cf1 + (g + 8) * cfw + col0) = make_float2(d12, d13);
        }
    }
}

#define SUBBAR() asm volatile("bar.sync %0, 128;" :: "r"(sub + 1) : "memory")
#define XSH(e) (subw + 0    + (e)*288)
#define XCH(e) (subw + 576  + (e)*576)
#define AOH(e) (subw + 1728 + (e)*576)
#define QVH(e) (subw + 2880 + (e)*1088)
#define VPW(e) (subw + 5056 + (e)*768)
#define XCF(e) ((float*)(subw + 6592 + (e)*1088))
#define PP(e)  ((float*)(subw + 8768 + (e)*128))

__global__ void __launch_bounds__(512, 1)
edge_kernel(const int* __restrict__ ei, int dir,
            const float* __restrict__ bpw, const float* __restrict__ bpb,
            const float* __restrict__ ipw, const float* __restrict__ ipb,
            const float* __restrict__ opw, const float* __restrict__ opb,
            const float* __restrict__ ln1g, const float* __restrict__ ln1b,
            const float* __restrict__ ln2g, const float* __restrict__ ln2b,
            const float* __restrict__ w1,  const float* __restrict__ fb1,
            const float* __restrict__ w2,  const float* __restrict__ fb2) {
    extern __shared__ float sm[];
    unsigned* smw = (unsigned*)sm;
    float* s_b = sm;
    __half* whq = (__half*)(smw + OFF_WQ);
    __half* who = (__half*)(smw + OFF_WO);
    __half* wh1 = (__half*)(smw + OFF_W1);
    __half* wh2 = (__half*)(smw + OFF_W2);
    __half* whb = (__half*)(smw + OFF_WB);

    const float* hin  = dir ? g_hB : g_hA;
    float*       hout = dir ? g_hA : g_hB;
    const int tid = threadIdx.x;

    for (int i = tid; i < 192 * 64; i += 512)
        whq[(i >> 6) * 72 + (i & 63)] = __float2half_rn(ipw[i]);
    for (int i = tid; i < 64 * 64; i += 512) {
        int r = (i >> 6) * 72 + (i & 63);
        who[r] = __float2half_rn(opw[i]);
        wh1[r] = __float2half_rn(w1[i]);
        wh2[r] = __float2half_rn(w2[i]);
        whb[r] = __float2half_rn(bpw[i]);
    }
    for (int i = tid; i < 192; i += 512) s_b[i] = ipb[i];
    if (tid < 64) {
        s_b[192 + tid] = opb[tid];  s_b[256 + tid] = fb1[tid];
        s_b[320 + tid] = fb2[tid];  s_b[384 + tid] = ln1g[tid];
        s_b[448 + tid] = ln1b[tid]; s_b[512 + tid] = ln2g[tid];
        s_b[576 + tid] = ln2b[tid]; s_b[640 + tid] = bpb[tid];
    }
    __syncthreads();

    const int sub  = tid >> 7;
    const int st   = tid & 127;
    const int warp = st >> 5;
    const int lane = st & 31;
    const int g    = lane >> 2, tg = lane & 3;
    unsigned* subw = smw + OFF_ACT + sub * SUBW;

    const unsigned* Wq  = smw + OFF_WQ;
    const unsigned* Wo  = smw + OFF_WO;
    const unsigned* W1p = smw + OFF_W1;
    const unsigned* W2p = smw + OFF_W2;
    const unsigned* Wb  = smw + OFF_WB;

    const int is64 = (g_any == 0);
    const int r0 = st >> 4, d0 = (st & 15) << 2;
    const int stride8 = gridDim.x * 8;

    // prologue prefetch (2 edges)
    bool pv0, pv1; int pt0 = 0, pt1 = 0; float pc0 = 0.f, pc1 = 0.f;
    float4 pvi0 = make_float4(0,0,0,0), pvj0 = pvi0, pvi1 = pvi0, pvj1 = pvi0;
    {
        int e0 = blockIdx.x * 8 + sub * 2;
        pv0 = e0 < EE; pv1 = (e0 + 1) < EE;
        if (pv0) {
            int s0 = is64 ? ei[2 * e0] : ei[e0];
            pt0    = is64 ? ei[2 * (EE + e0)] : ei[EE + e0];
            pc0 = g_inv[pt0];
            pvi0 = *(const float4*)(hin + (size_t)pt0 * 512 + r0 * 64 + d0);
            pvj0 = *(const float4*)(hin + (size_t)s0  * 512 + r0 * 64 + d0);
        }
        if (pv1) {
            int e1 = e0 + 1;
            int s1 = is64 ? ei[2 * e1] : ei[e1];
            pt1    = is64 ? ei[2 * (EE + e1)] : ei[EE + e1];
            pc1 = g_inv[pt1];
            pvi1 = *(const float4*)(hin + (size_t)pt1 * 512 + r0 * 64 + d0);
            pvj1 = *(const float4*)(hin + (size_t)s1  * 512 + r0 * 64 + d0);
        }
    }

    for (int base = blockIdx.x * 8; base < EE; base += stride8) {
        const bool v0 = pv0, v1 = pv1;
        const int  t0i = pt0, t1i = pt1;
        const float c0i = pc0, c1i = pc1;

        // P0: commit gathers
        if (v0) {
            *(float4*)(XCF(0) + r0 * 68 + d0) = pvi0;
            int wb = r0 * 36 + (d0 >> 1);
            XCH(0)[wb]     = packh2(pvi0.y, pvi0.x);
            XCH(0)[wb + 1] = packh2(pvi0.w, pvi0.z);
            XSH(0)[wb]     = packh2(pvj0.y, pvj0.x);
            XSH(0)[wb + 1] = packh2(pvj0.w, pvj0.z);
        }
        if (v1) {
            *(float4*)(XCF(1) + r0 * 68 + d0) = pvi1;
            int wb = r0 * 36 + (d0 >> 1);
            XCH(1)[wb]     = packh2(pvi1.y, pvi1.x);
            XCH(1)[wb + 1] = packh2(pvi1.w, pvi1.z);
            XSH(1)[wb]     = packh2(pvj1.y, pvj1.x);
            XSH(1)[wb + 1] = packh2(pvj1.w, pvj1.z);
        }
        SUBBAR();

        // prefetch next iteration
        {
            int e0 = base + stride8 + sub * 2;
            pv0 = e0 < EE; pv1 = (e0 + 1) < EE;
            if (pv0) {
                int s0 = is64 ? ei[2 * e0] : ei[e0];
                pt0    = is64 ? ei[2 * (EE + e0)] : ei[EE + e0];
                pc0 = g_inv[pt0];
                pvi0 = *(const float4*)(hin + (size_t)pt0 * 512 + r0 * 64 + d0);
                pvj0 = *(const float4*)(hin + (size_t)s0  * 512 + r0 * 64 + d0);
            }
            if (pv1) {
                int e1 = e0 + 1;
                int s1 = is64 ? ei[2 * e1] : ei[e1];
                pt1    = is64 ? ei[2 * (EE + e1)] : ei[EE + e1];
                pc1 = g_inv[pt1];
                pvi1 = *(const float4*)(hin + (size_t)pt1 * 512 + r0 * 64 + d0);
                pvj1 = *(const float4*)(hin + (size_t)s1  * 512 + r0 * 64 + d0);
            }
        }

        // P1: bproj (both edges) -> rows 8..15 of XCH/XCF
        if (v0) {
            unsigned a0[4][4], a1[4][4];
            load_ah(a0, XSH(0), lane);
            load_ah(a1, XSH(1), lane);
            gemm2<0, true, true, true>(a0, a1, Wb, s_b + 640, warp * 16,
                XCH(0) + 8 * 36, XCH(1) + 8 * 36, 36,
                XCF(0) + 8 * 68, XCF(1) + 8 * 68, 68, 0, 0, 0, lane);
            gemm2<0, true, true, true>(a0, a1, Wb, s_b + 640, warp * 16 + 8,
                XCH(0) + 8 * 36, XCH(1) + 8 * 36, 36,
                XCF(0) + 8 * 68, XCF(1) + 8 * 68, 68, 0, 0, 0, lane);
        }
        SUBBAR();

        // P2+P3 fused: warp computes ITS OWN head's q/k/v, then its attention.
        if (v0) {
            unsigned a0[4][4], a1[4][4];
            load_ah(a0, XCH(0), lane);
            load_ah(a1, XCH(1), lane);
            #pragma unroll
            for (int nt = 0; nt < 6; nt++) {
                int jb = (nt < 2) ? (warp * 16 + nt * 8)
                       : (nt < 4) ? (64 + warp * 16 + (nt - 2) * 8)
                                  : (128 + warp * 16 + (nt - 4) * 8);
                int col0 = jb + 2 * tg;
                float2 bb = *(const float2*)(s_b + col0);
                float d00 = bb.x, d01 = bb.y, d02 = bb.x, d03 = bb.y;
                float d10 = bb.x, d11 = bb.y, d12 = bb.x, d13 = bb.y;
                const unsigned* wr = Wq + (jb + g) * 36 + tg;
                unsigned b0[4], b1[4];
                #pragma unroll
                for (int kc = 0; kc < 4; kc++) { b0[kc] = wr[kc * 8]; b1[kc] = wr[kc * 8 + 4]; }
                #pragma unroll
                for (int kc = 0; kc < 4; kc++)
                    mma_f16(d00, d01, d02, d03, a0[kc][0], a0[kc][1], a0[kc][2], a0[kc][3], b0[kc], b1[kc]);
                #pragma unroll
                for (int kc = 0; kc < 4; kc++)
                    mma_f16(d10, d11, d12, d13, a1[kc][0], a1[kc][1], a1[kc][2], a1[kc][3], b0[kc], b1[kc]);
                if (jb < 128) {
                    QVH(0)[g * 68 + (jb >> 1) + tg]       = packh2(d01, d00);
                    QVH(0)[(g + 8) * 68 + (jb >> 1) + tg] = packh2(d03, d02);
                    QVH(1)[g * 68 + (jb >> 1) + tg]       = packh2(d11, d10);
                    QVH(1)[(g + 8) * 68 + (jb >> 1) + tg] = packh2(d13, d12);
                } else {
                    int dL = jb - 128 + 2 * tg;
                    __half* vp0 = (__half*)VPW(0);
                    __half* vp1 = (__half*)VPW(1);
                    vp0[dL * 24 + g]           = __float2half_rn(d00);
                    vp0[(dL + 1) * 24 + g]     = __float2half_rn(d01);
                    vp0[dL * 24 + g + 8]       = __float2half_rn(d02);
                    vp0[(dL + 1) * 24 + g + 8] = __float2half_rn(d03);
                    vp1[dL * 24 + g]           = __float2half_rn(d10);
                    vp1[(dL + 1) * 24 + g]     = __float2half_rn(d11);
                    vp1[dL * 24 + g + 8]       = __float2half_rn(d12);
                    vp1[(dL + 1) * 24 + g + 8] = __float2half_rn(d13);
                }
            }
            __syncwarp();

            // P3: attention for head `warp` (both edges), P in registers
            #pragma unroll
            for (int e = 0; e < 2; e++) {
                const unsigned* qb = QVH(e) + warp * 8;
                const unsigned* kb = QVH(e) + 32 + warp * 8;
                unsigned a0q = qb[g * 68 + tg],     a1q = qb[(g + 8) * 68 + tg];
                unsigned a2q = qb[g * 68 + tg + 4], a3q = qb[(g + 8) * 68 + tg + 4];
                float s00 = 0, s01 = 0, s02 = 0, s03 = 0;
                float s10 = 0, s11 = 0, s12 = 0, s13 = 0;
                mma_f16(s00, s01, s02, s03, a0q, a1q, a2q, a3q,
                        kb[g * 68 + tg], kb[g * 68 + tg + 4]);
                mma_f16(s10, s11, s12, s13, a0q, a1q, a2q, a3q,
                        kb[(g + 8) * 68 + tg], kb[(g + 8) * 68 + tg + 4]);
                s00 *= 0.25f; s01 *= 0.25f; s02 *= 0.25f; s03 *= 0.25f;
                s10 *= 0.25f; s11 *= 0.25f; s12 *= 0.25f; s13 *= 0.25f;
                float m0 = fmaxf(fmaxf(s00, s01), fmaxf(s10, s11));
                float m1 = fmaxf(fmaxf(s02, s03), fmaxf(s12, s13));
                m0 = fmaxf(m0, __shfl_xor_sync(0xffffffffu, m0, 1));
                m0 = fmaxf(m0, __shfl_xor_sync(0xffffffffu, m0, 2));
                m1 = fmaxf(m1, __shfl_xor_sync(0xffffffffu, m1, 1));
                m1 = fmaxf(m1, __shfl_xor_sync(0xffffffffu, m1, 2));
                float e00 = __expf(s00 - m0), e01 = __expf(s01 - m0);
                float e10 = __expf(s10 - m0), e11 = __expf(s11 - m0);
                float e02 = __expf(s02 - m1), e03 = __expf(s03 - m1);
                float e12 = __expf(s12 - m1), e13 = __expf(s13 - m1);
                float t0 = (e00 + e01) + (e10 + e11);
                float t1 = (e02 + e03) + (e12 + e13);
                t0 += __shfl_xor_sync(0xffffffffu, t0, 1);
                t0 += __shfl_xor_sync(0xffffffffu, t0, 2);
                t1 += __shfl_xor_sync(0xffffffffu, t1, 1);
                t1 += __shfl_xor_sync(0xffffffffu, t1, 2);
                float r0s = 1.f / t0, r1s = 1.f / t1;
                unsigned ap0 = packh2(e01 * r0s, e00 * r0s);
                unsigned ap1 = packh2(e03 * r1s, e02 * r1s);
                unsigned ap2 = packh2(e11 * r0s, e10 * r0s);
                unsigned ap3 = packh2(e13 * r1s, e12 * r1s);
                const unsigned* vb = VPW(e) + warp * 192;
                unsigned* ao = AOH(e);
                #pragma unroll
                for (int jb2 = 0; jb2 < 2; jb2++) {
                    float c0 = 0, c1 = 0, c2 = 0, c3 = 0;
                    const unsigned* vr = vb + (jb2 * 8 + g) * 12 + tg;
                    mma_f16(c0, c1, c2, c3, ap0, ap1, ap2, ap3, vr[0], vr[4]);
                    ao[g * 36 + warp * 8 + jb2 * 4 + tg]       = packh2(c1, c0);
                    ao[(g + 8) * 36 + warp * 8 + jb2 * 4 + tg] = packh2(c3, c2);
                }
            }
        }
        SUBBAR();

        // P4: out_proj + residual, register-resident; emit LN1 partials
        float p4[2][8];
        if (v0) {
            unsigned a0[4][4], a1[4][4];
            load_ah(a0, AOH(0), lane);
            load_ah(a1, AOH(1), lane);
            #pragma unroll
            for (int jt = 0; jt < 2; jt++) {
                int jb = warp * 16 + jt * 8;
                int col0 = jb + 2 * tg;
                float2 bb = *(const float2*)(s_b + 192 + col0);
                float d00 = bb.x, d01 = bb.y, d02 = bb.x, d03 = bb.y;
                float d10 = bb.x, d11 = bb.y, d12 = bb.x, d13 = bb.y;
                const unsigned* wr = Wo + (jb + g) * 36 + tg;
                unsigned b0[4], b1[4];
                #pragma unroll
                for (int kc = 0; kc < 4; kc++) { b0[kc] = wr[kc * 8]; b1[kc] = wr[kc * 8 + 4]; }
                #pragma unroll
                for (int kc = 0; kc < 4; kc++)
                    mma_f16(d00, d01, d02, d03, a0[kc][0], a0[kc][1], a0[kc][2], a0[kc][3], b0[kc], b1[kc]);
                #pragma unroll
                for (int kc = 0; kc < 4; kc++)
                    mma_f16(d10, d11, d12, d13, a1[kc][0], a1[kc][1], a1[kc][2], a1[kc][3], b0[kc], b1[kc]);
                float2 r00 = *(const float2*)(XCF(0) + g * 68 + col0);
                float2 r01 = *(const float2*)(XCF(0) + (g + 8) * 68 + col0);
                float2 r10 = *(const float2*)(XCF(1) + g * 68 + col0);
                float2 r11 = *(const float2*)(XCF(1) + (g + 8) * 68 + col0);
                p4[0][jt * 4 + 0] = d00 + r00.x; p4[0][jt * 4 + 1] = d01 + r00.y;
                p4[0][jt * 4 + 2] = d02 + r01.x; p4[0][jt * 4 + 3] = d03 + r01.y;
                p4[1][jt * 4 + 0] = d10 + r10.x; p4[1][jt * 4 + 1] = d11 + r10.y;
                p4[1][jt * 4 + 2] = d12 + r11.x; p4[1][jt * 4 + 3] = d13 + r11.y;
            }
            #pragma unroll
            for (int e = 0; e < 2; e++) {
                float sg  = (p4[e][0] + p4[e][1]) + (p4[e][4] + p4[e][5]);
                float sg8 = (p4[e][2] + p4[e][3]) + (p4[e][6] + p4[e][7]);
                float qg  = p4[e][0]*p4[e][0] + p4[e][1]*p4[e][1] + p4[e][4]*p4[e][4] + p4[e][5]*p4[e][5];
                float qg8 = p4[e][2]*p4[e][2] + p4[e][3]*p4[e][3] + p4[e][6]*p4[e][6] + p4[e][7]*p4[e][7];
                sg  += __shfl_xor_sync(0xffffffffu, sg, 1);  sg  += __shfl_xor_sync(0xffffffffu, sg, 2);
                sg8 += __shfl_xor_sync(0xffffffffu, sg8, 1); sg8 += __shfl_xor_sync(0xffffffffu, sg8, 2);
                qg  += __shfl_xor_sync(0xffffffffu, qg, 1);  qg  += __shfl_xor_sync(0xffffffffu, qg, 2);
                qg8 += __shfl_xor_sync(0xffffffffu, qg8, 1); qg8 += __shfl_xor_sync(0xffffffffu, qg8, 2);
                if (tg == 0) {
                    float* ppe = PP(e);
                    ppe[g * 8 + warp]           = sg;
                    ppe[g * 8 + 4 + warp]       = qg;
                    ppe[(g + 8) * 8 + warp]     = sg8;
                    ppe[(g + 8) * 8 + 4 + warp] = qg8;
                }
            }
        }
        SUBBAR();

        // LN1 finish: combine partials, normalize registers, write XCF(rows0-7) + XCH
        if (v0) {
            #pragma unroll
            for (int e = 0; e < 2; e++) {
                float* ppe = PP(e);
                float4 sx  = *(const float4*)(ppe + g * 8);
                float4 sq  = *(const float4*)(ppe + g * 8 + 4);
                float4 sx8 = *(const float4*)(ppe + (g + 8) * 8);
                float4 sq8 = *(const float4*)(ppe + (g + 8) * 8 + 4);
                float mu   = ((sx.x + sx.y) + (sx.z + sx.w)) * 0.015625f;
                float ex2  = ((sq.x + sq.y) + (sq.z + sq.w)) * 0.015625f;
                float mu8  = ((sx8.x + sx8.y) + (sx8.z + sx8.w)) * 0.015625f;
                float ex28 = ((sq8.x + sq8.y) + (sq8.z + sq8.w)) * 0.015625f;
                float rstd  = rsqrtf(ex2 - mu * mu + 1e-5f);
                float rstd8 = rsqrtf(ex28 - mu8 * mu8 + 1e-5f);
                #pragma unroll
                for (int jt = 0; jt < 2; jt++) {
                    int jb = warp * 16 + jt * 8;
                    int col0 = jb + 2 * tg;
                    float2 gg = *(const float2*)(s_b + 384 + col0);
                    float2 be = *(const float2*)(s_b + 448 + col0);
                    float o0 = (p4[e][jt * 4 + 0] - mu) * rstd * gg.x + be.x;
                    float o1 = (p4[e][jt * 4 + 1] - mu) * rstd * gg.y + be.y;
                    float o2 = (p4[e][jt * 4 + 2] - mu8) * rstd8 * gg.x + be.x;
                    float o3 = (p4[e][jt * 4 + 3] - mu8) * rstd8 * gg.y + be.y;
                    *(float2*)(XCF(e) + g * 68 + col0) = make_float2(o0, o1);
                    XCH(e)[g * 36 + (jb >> 1) + tg]       = packh2(o1, o0);
                    XCH(e)[(g + 8) * 36 + (jb >> 1) + tg] = packh2(o3, o2);
                }
            }
        }
        SUBBAR();

        // P6: FF1 + relu -> AOH
        if (v0) {
            unsigned a0[4][4], a1[4][4];
            load_ah(a0, XCH(0), lane);
            load_ah(a1, XCH(1), lane);
            gemm2<1, false, true, false>(a0, a1, W1p, s_b + 256, warp * 16,
                AOH(0), AOH(1), 36, 0, 0, 0, 0, 0, 0, lane);
            gemm2<1, false, true, false>(a0, a1, W1p, s_b + 256, warp * 16 + 8,
                AOH(0), AOH(1), 36, 0, 0, 0, 0, 0, 0, lane);
        }
        SUBBAR();

        // P7: FF2 + residual (rows 0..7 only), register-resident; LN2 partials
        float p7[2][4];
        if (v0) {
            unsigned a0[4][4], a1[4][4];
            load_ah(a0, AOH(0), lane);
            load_ah(a1, AOH(1), lane);
            #pragma unroll
            for (int jt = 0; jt < 2; jt++) {
                int jb = warp * 16 + jt * 8;
                int col0 = jb + 2 * tg;
                float2 bb = *(const float2*)(s_b + 320 + col0);
                float d00 = bb.x, d01 = bb.y, d02 = bb.x, d03 = bb.y;
                float d10 = bb.x, d11 = bb.y, d12 = bb.x, d13 = bb.y;
                const unsigned* wr = W2p + (jb + g) * 36 + tg;
                unsigned b0[4], b1[4];
                #pragma unroll
                for (int kc = 0; kc < 4; kc++) { b0[kc] = wr[kc * 8]; b1[kc] = wr[kc * 8 + 4]; }
                #pragma unroll
                for (int kc = 0; kc < 4; kc++)
                    mma_f16(d00, d01, d02, d03, a0[kc][0], a0[kc][1], a0[kc][2], a0[kc][3], b0[kc], b1[kc]);
                #pragma unroll
                for (int kc = 0; kc < 4; kc++)
                    mma_f16(d10, d11, d12, d13, a1[kc][0], a1[kc][1], a1[kc][2], a1[kc][3], b0[kc], b1[kc]);
                float2 r0v = *(const float2*)(XCF(0) + g * 68 + col0);
                float2 r1v = *(const float2*)(XCF(1) + g * 68 + col0);
                p7[0][jt * 2 + 0] = d00 + r0v.x; p7[0][jt * 2 + 1] = d01 + r0v.y;
                p7[1][jt * 2 + 0] = d10 + r1v.x; p7[1][jt * 2 + 1] = d11 + r1v.y;
            }
            #pragma unroll
            for (int e = 0; e < 2; e++) {
                float sg = (p7[e][0] + p7[e][1]) + (p7[e][2] + p7[e][3]);
                float qg = p7[e][0]*p7[e][0] + p7[e][1]*p7[e][1] + p7[e][2]*p7[e][2] + p7[e][3]*p7[e][3];
                sg += __shfl_xor_sync(0xffffffffu, sg, 1); sg += __shfl_xor_sync(0xffffffffu, sg, 2);
                qg += __shfl_xor_sync(0xffffffffu, qg, 1); qg += __shfl_xor_sync(0xffffffffu, qg, 2);
                if (tg == 0) {
                    float* ppe = PP(e);
                    ppe[g * 8 + warp]     = sg;
                    ppe[g * 8 + 4 + warp] = qg;
                }
            }
        }
        SUBBAR();

        // LN2 finish + scaled RED.128 scatter (rows 0..7): lane pairs form quads
        #pragma unroll
        for (int e = 0; e < 2; e++) {
            bool ve = e ? v1 : v0;
            if (!ve) continue;
            int tgte = e ? t1i : t0i;
            float ice = e ? c1i : c0i;
            float* ppe = PP(e);
            float4 sx = *(const float4*)(ppe + g * 8);
            float4 sq = *(const float4*)(ppe + g * 8 + 4);
            float mu  = ((sx.x + sx.y) + (sx.z + sx.w)) * 0.015625f;
            float ex2 = ((sq.x + sq.y) + (sq.z + sq.w)) * 0.015625f;
            float rstd = rsqrtf(ex2 - mu * mu + 1e-5f);
            #pragma unroll
            for (int jt = 0; jt < 2; jt++) {
                int col0 = warp * 16 + jt * 8 + 2 * tg;
                float2 gg = *(const float2*)(s_b + 512 + col0);
                float2 be = *(const float2*)(s_b + 576 + col0);
                float o0 = ((p7[e][jt * 2 + 0] - mu) * rstd * gg.x + be.x) * ice;
                float o1 = ((p7[e][jt * 2 + 1] - mu) * rstd * gg.y + be.y) * ice;
                // pair lanes (tg, tg^1) to form a contiguous 4-col quad
                float o0p = __shfl_xor_sync(0xffffffffu, o0, 1);
                float o1p = __shfl_xor_sync(0xffffffffu, o1, 1);
                if ((tg & 1) == 0) {
                    float* dst = hout + (size_t)tgte * 512 + g * 64
                               + warp * 16 + jt * 8 + ((tg & 2) << 1);
                    asm volatile("red.global.add.v4.f32 [%0], {%1,%2,%3,%4};"
                                 :: "l"(dst), "f"(o0), "f"(o1), "f"(o0p), "f"(o1p)
                                 : "memory");
                }
            }
        }
        // no trailing barrier: LN2 reads PP (next written at P4, barriers away);
        // next P0 writes XSH/XCH/XCF rows 0..7, last read at P7 (behind barrier).
    }
}

__global__ void out_kernel(const float* __restrict__ ow, const float* __restrict__ ob,
                           float* __restrict__ out) {
    __shared__ float shs[8][64];
    int w = threadIdx.x >> 5, lane = threadIdx.x & 31;
    int n = blockIdx.x * 8 + w;
    if (n >= NN) return;
    const float* hr = g_hA + (size_t)n * 512;
    float lo = 0.f, hi = 0.f;
    #pragma unroll
    for (int c = 0; c < 8; c++) { lo += hr[c * 64 + lane]; hi += hr[c * 64 + 32 + lane]; }
    shs[w][lane] = lo; shs[w][lane + 32] = hi;
    __syncwarp();
    float z = -1e30f;
    if (lane < 16) {
        float acc = 8.f * ob[lane];
        const float* wr = ow + lane * 64;
        #pragma unroll
        for (int d = 0; d < 64; d++) acc = fmaf(shs[w][d], wr[d], acc);
        z = acc;
    }
    float m = z;
    #pragma unroll
    for (int off = 8; off; off >>= 1) m = fmaxf(m, __shfl_xor_sync(0xffffffffu, m, off, 16));
    float p = __expf(z - m);
    float s = p;
    #pragma unroll
    for (int off = 8; off; off >>= 1) s += __shfl_xor_sync(0xffffffffu, s, off, 16);
    if (lane < 16) out[n * 16 + lane] = p / s;
}

extern "C" void kernel_launch(void* const* d_in, const int* in_sizes, int n_in,
                              void* d_out, int out_size) {
    const float* x    = (const float*)d_in[0];
    const int*   ei   = (const int*)d_in[1];
    const float* numw = (const float*)d_in[2];
    const float* numb = (const float*)d_in[3];
    const float* bpw  = (const float*)d_in[4];
    const float* bpb  = (const float*)d_in[5];
    const float* ipw  = (const float*)d_in[6];
    const float* ipb  = (const float*)d_in[7];
    const float* opw  = (const float*)d_in[8];
    const float* opb  = (const float*)d_in[9];
    const float* g1   = (const float*)d_in[10];
    const float* b1   = (const float*)d_in[11];
    const float* g2   = (const float*)d_in[12];
    const float* b2   = (const float*)d_in[13];
    const float* w1   = (const float*)d_in[14];
    const float* fb1  = (const float*)d_in[15];
    const float* w2   = (const float*)d_in[16];
    const float* fb2  = (const float*)d_in[17];
    const float* ow   = (const float*)d_in[18];
    const float* ob   = (const float*)d_in[19];
    float* out = (float*)d_out;

    const int SMEM_BYTES = SMEM_WORDS * 4;
    cudaFuncSetAttribute(edge_kernel, cudaFuncAttributeMaxDynamicSharedMemorySize, SMEM_BYTES);

    int dev = 0, sms = 148;
    cudaGetDevice(&dev);
    cudaDeviceGetAttribute(&sms, cudaDevAttrMultiProcessorCount, dev);

    setup0_kernel<<<(NN * 128 + 255) / 256, 256>>>();
    detect_kernel<<<256, 256>>>(ei);
    embed_kernel<<<(NN * 512 + 255) / 256, 256>>>(x, numw, numb);
    count_kernel<<<(EE + 255) / 256, 256>>>(ei);
    fin_cnt_kernel<<<(NN + 255) / 256, 256>>>();

    edge_kernel<<<sms, 512, SMEM_BYTES>>>(ei, 0,
        bpw, bpb, ipw, ipb, opw, opb, g1, b1, g2, b2, w1, fb1, w2, fb2);

    zeroA_kernel<<<(NN * 128 + 255) / 256, 256>>>();
    edge_kernel<<<sms, 512, SMEM_BYTES>>>(ei, 1,
        bpw + 64 * 64, bpb + 64, ipw + 192 * 64, ipb + 192, opw + 64 * 64, opb + 64,
        g1 + 64, b1 + 64, g2 + 64, b2 + 64,
        w1 + 64 * 64, fb1 + 64, w2 + 64 * 64, fb2 + 64);

    out_kernel<<<(NN + 7) / 8, 256>>>(ow, ob, out);
}

// round 17
// speedup vs baseline: 1.1707x; 1.1689x over previous
#include <cuda_runtime.h>
#include <cuda_fp16.h>

#define NN 50000
#define EE 100000

// word offsets in dynamic smem
#define OFF_WQ  704
#define OFF_WO  (OFF_WQ + 192*36)
#define OFF_W1  (OFF_WO + 64*36)
#define OFF_W2  (OFF_W1 + 64*36)
#define OFF_WB  (OFF_W2 + 64*36)
#define OFF_ACT (OFF_WB + 64*36)     // 16832
// per-sub (words): xsh 0(2x288) xch 576(2x576) aohp 1728(576)
//   qvh 2880(2x1088)  [after P3: xlnh overlays qvh0, xlnf overlays qvh1]
//   vpw 5056(2x768) xcf 6592(2x1088 f32) pp 8768(128 f32)
#define SUBW 9024
#define SMEM_WORDS (OFF_ACT + 4*SUBW)

__device__ float g_hA[(size_t)NN * 512];
__device__ float g_hB[(size_t)NN * 512];
__device__ float g_inv[NN];
__device__ int   g_any;

__global__ void setup0_kernel() {
    size_t i = (size_t)blockIdx.x * blockDim.x + threadIdx.x;
    if (i == 0) g_any = 0;
    if (i < NN) g_inv[i] = 0.f;
    if (i < (size_t)NN * 128) ((float4*)g_hB)[i] = make_float4(0.f, 0.f, 0.f, 0.f);
}
__global__ void detect_kernel(const int* __restrict__ ei) {
    int i = blockIdx.x * blockDim.x + threadIdx.x;
    int v = 0;
    for (int k = i; k < EE; k += gridDim.x * blockDim.x) v |= ei[2 * k + 1];
    if (v) atomicOr(&g_any, 1);
}
__global__ void embed_kernel(const float* __restrict__ x, const float* __restrict__ nw,
                             const float* __restrict__ nb) {
    int i = blockIdx.x * blockDim.x + threadIdx.x;
    if (i < NN * 512) {
        int n = i >> 9, r = i & 511;
        g_hA[i] = x[n * 8 + (r >> 6)] * nw[r] + nb[r];
    }
}
__global__ void count_kernel(const int* __restrict__ ei) {
    int e = blockIdx.x * blockDim.x + threadIdx.x;
    if (e < EE) {
        int t = (g_any == 0) ? ei[2 * (EE + e)] : ei[EE + e];
        atomicAdd(&g_inv[t], 1.0f);
    }
}
__global__ void fin_cnt_kernel() {
    int i = blockIdx.x * blockDim.x + threadIdx.x;
    if (i < NN) g_inv[i] = 1.0f / fmaxf(g_inv[i], 1.0f);
}
__global__ void zeroA_kernel() {
    size_t i = (size_t)blockIdx.x * blockDim.x + threadIdx.x;
    if (i < (size_t)NN * 128) ((float4*)g_hA)[i] = make_float4(0.f, 0.f, 0.f, 0.f);
}

// ---- f16 mma helpers ----
__device__ __forceinline__ void mma_f16(float& c0, float& c1, float& c2, float& c3,
                                        unsigned a0, unsigned a1, unsigned a2, unsigned a3,
                                        unsigned b0, unsigned b1) {
    asm volatile(
        "mma.sync.aligned.m16n8k16.row.col.f32.f16.f16.f32 "
        "{%0,%1,%2,%3}, {%4,%5,%6,%7}, {%8,%9}, {%0,%1,%2,%3};\n"
        : "+f"(c0), "+f"(c1), "+f"(c2), "+f"(c3)
        : "r"(a0), "r"(a1), "r"(a2), "r"(a3), "r"(b0), "r"(b1));
}
__device__ __forceinline__ unsigned packh2(float hi, float lo) {
    unsigned d;
    asm("cvt.rn.f16x2.f32 %0, %1, %2;" : "=r"(d) : "f"(hi), "f"(lo));
    return d;
}
__device__ __forceinline__ void load_ah(unsigned a[4][4], const unsigned* __restrict__ X,
                                        int lane) {
    int row = lane >> 2, tg = lane & 3;
    const unsigned* p0 = X + row * 36 + tg;
    const unsigned* p1 = X + (row + 8) * 36 + tg;
    #pragma unroll
    for (int kc = 0; kc < 4; kc++) {
        a[kc][0] = p0[kc * 8];
        a[kc][1] = p1[kc * 8];
        a[kc][2] = p0[kc * 8 + 4];
        a[kc][3] = p1[kc * 8 + 4];
    }
}

// two-edge tile (used by P1/P2 where all 16 rows per edge are live)
template<int EPI, bool ROWS8>
__device__ __forceinline__ void gemm2h(const unsigned a0[4][4], const unsigned a1[4][4],
                                       const unsigned* __restrict__ W,
                                       const float* __restrict__ bias, int jbase,
                                       unsigned* Ch0, unsigned* Ch1, int chw, int lane) {
    int g = lane >> 2, tg = lane & 3;
    int col0 = jbase + 2 * tg;
    float2 bb = *(const float2*)(bias + col0);
    float d00 = bb.x, d01 = bb.y, d02 = bb.x, d03 = bb.y;
    float d10 = bb.x, d11 = bb.y, d12 = bb.x, d13 = bb.y;
    const unsigned* wr = W + (jbase + g) * 36 + tg;
    unsigned b0[4], b1[4];
    #pragma unroll
    for (int kc = 0; kc < 4; kc++) { b0[kc] = wr[kc * 8]; b1[kc] = wr[kc * 8 + 4]; }
    #pragma unroll
    for (int kc = 0; kc < 4; kc++)
        mma_f16(d00, d01, d02, d03, a0[kc][0], a0[kc][1], a0[kc][2], a0[kc][3], b0[kc], b1[kc]);
    #pragma unroll
    for (int kc = 0; kc < 4; kc++)
        mma_f16(d10, d11, d12, d13, a1[kc][0], a1[kc][1], a1[kc][2], a1[kc][3], b0[kc], b1[kc]);
    if (EPI == 1) {
        d00 = fmaxf(d00, 0.f); d01 = fmaxf(d01, 0.f); d02 = fmaxf(d02, 0.f); d03 = fmaxf(d03, 0.f);
        d10 = fmaxf(d10, 0.f); d11 = fmaxf(d11, 0.f); d12 = fmaxf(d12, 0.f); d13 = fmaxf(d13, 0.f);
    }
    Ch0[g * chw + (jbase >> 1) + tg] = packh2(d01, d00);
    Ch1[g * chw + (jbase >> 1) + tg] = packh2(d11, d10);
    if (!ROWS8) {
        Ch0[(g + 8) * chw + (jbase >> 1) + tg] = packh2(d03, d02);
        Ch1[(g + 8) * chw + (jbase >> 1) + tg] = packh2(d13, d12);
    }
}

#define SUBBAR() asm volatile("bar.sync %0, 128;" :: "r"(sub + 1) : "memory")
#define XSH(e) (subw + 0    + (e)*288)
#define XCH(e) (subw + 576  + (e)*576)
#define AOHP   (subw + 1728)                   // packed: rows 0-7 edge0, 8-15 edge1
#define QVH(e) (subw + 2880 + (e)*1088)
#define XLNH   (subw + 2880)                   // overlays QVH(0) after P3
#define XLNF   ((float*)(subw + 3968))         // overlays QVH(1) after P3 (16x68 f32)
#define VPW(e) (subw + 5056 + (e)*768)
#define XCF(e) ((float*)(subw + 6592 + (e)*1088))
#define PPB    ((float*)(subw + 8768))         // 128 f32 partials (packed rows)

__global__ void __launch_bounds__(512, 1)
edge_kernel(const int* __restrict__ ei, int dir,
            const float* __restrict__ bpw, const float* __restrict__ bpb,
            const float* __restrict__ ipw, const float* __restrict__ ipb,
            const float* __restrict__ opw, const float* __restrict__ opb,
            const float* __restrict__ ln1g, const float* __restrict__ ln1b,
            const float* __restrict__ ln2g, const float* __restrict__ ln2b,
            const float* __restrict__ w1,  const float* __restrict__ fb1,
            const float* __restrict__ w2,  const float* __restrict__ fb2) {
    extern __shared__ float sm[];
    unsigned* smw = (unsigned*)sm;
    float* s_b = sm;
    __half* whq = (__half*)(smw + OFF_WQ);
    __half* who = (__half*)(smw + OFF_WO);
    __half* wh1 = (__half*)(smw + OFF_W1);
    __half* wh2 = (__half*)(smw + OFF_W2);
    __half* whb = (__half*)(smw + OFF_WB);

    const float* hin  = dir ? g_hB : g_hA;
    float*       hout = dir ? g_hA : g_hB;
    const int tid = threadIdx.x;

    for (int i = tid; i < 192 * 64; i += 512)
        whq[(i >> 6) * 72 + (i & 63)] = __float2half_rn(ipw[i]);
    for (int i = tid; i < 64 * 64; i += 512) {
        int r = (i >> 6) * 72 + (i & 63);
        who[r] = __float2half_rn(opw[i]);
        wh1[r] = __float2half_rn(w1[i]);
        wh2[r] = __float2half_rn(w2[i]);
        whb[r] = __float2half_rn(bpw[i]);
    }
    for (int i = tid; i < 192; i += 512) s_b[i] = ipb[i];
    if (tid < 64) {
        s_b[192 + tid] = opb[tid];  s_b[256 + tid] = fb1[tid];
        s_b[320 + tid] = fb2[tid];  s_b[384 + tid] = ln1g[tid];
        s_b[448 + tid] = ln1b[tid]; s_b[512 + tid] = ln2g[tid];
        s_b[576 + tid] = ln2b[tid]; s_b[640 + tid] = bpb[tid];
    }
    __syncthreads();

    const int sub  = tid >> 7;
    const int st   = tid & 127;
    const int warp = st >> 5;
    const int lane = st & 31;
    const int g    = lane >> 2, tg = lane & 3;
    unsigned* subw = smw + OFF_ACT + sub * SUBW;

    const unsigned* Wq  = smw + OFF_WQ;
    const unsigned* Wo  = smw + OFF_WO;
    const unsigned* W1p = smw + OFF_W1;
    const unsigned* W2p = smw + OFF_W2;
    const unsigned* Wb  = smw + OFF_WB;

    const int is64 = (g_any == 0);
    const int r0 = st >> 4, d0 = (st & 15) << 2;
    const int stride8 = gridDim.x * 8;

    // prologue prefetch (2 edges)
    bool pv0, pv1; int pt0 = 0, pt1 = 0; float pc0 = 0.f, pc1 = 0.f;
    float4 pvi0 = make_float4(0,0,0,0), pvj0 = pvi0, pvi1 = pvi0, pvj1 = pvi0;
    {
        int e0 = blockIdx.x * 8 + sub * 2;
        pv0 = e0 < EE; pv1 = (e0 + 1) < EE;
        if (pv0) {
            int s0 = is64 ? ei[2 * e0] : ei[e0];
            pt0    = is64 ? ei[2 * (EE + e0)] : ei[EE + e0];
            pc0 = g_inv[pt0];
            pvi0 = *(const float4*)(hin + (size_t)pt0 * 512 + r0 * 64 + d0);
            pvj0 = *(const float4*)(hin + (size_t)s0  * 512 + r0 * 64 + d0);
        }
        if (pv1) {
            int e1 = e0 + 1;
            int s1 = is64 ? ei[2 * e1] : ei[e1];
            pt1    = is64 ? ei[2 * (EE + e1)] : ei[EE + e1];
            pc1 = g_inv[pt1];
            pvi1 = *(const float4*)(hin + (size_t)pt1 * 512 + r0 * 64 + d0);
            pvj1 = *(const float4*)(hin + (size_t)s1  * 512 + r0 * 64 + d0);
        }
    }

    for (int base = blockIdx.x * 8; base < EE; base += stride8) {
        const bool v0 = pv0, v1 = pv1;
        const int  t0i = pt0, t1i = pt1;
        const float c0i = pc0, c1i = pc1;

        // P0: commit gathers (XCF rows 0..7 only: P4 residual; XCH rows 0..7; XSH)
        if (v0) {
            *(float4*)(XCF(0) + r0 * 68 + d0) = pvi0;
            int wb = r0 * 36 + (d0 >> 1);
            XCH(0)[wb]     = packh2(pvi0.y, pvi0.x);
            XCH(0)[wb + 1] = packh2(pvi0.w, pvi0.z);
            XSH(0)[wb]     = packh2(pvj0.y, pvj0.x);
            XSH(0)[wb + 1] = packh2(pvj0.w, pvj0.z);
        }
        if (v1) {
            *(float4*)(XCF(1) + r0 * 68 + d0) = pvi1;
            int wb = r0 * 36 + (d0 >> 1);
            XCH(1)[wb]     = packh2(pvi1.y, pvi1.x);
            XCH(1)[wb + 1] = packh2(pvi1.w, pvi1.z);
            XSH(1)[wb]     = packh2(pvj1.y, pvj1.x);
            XSH(1)[wb + 1] = packh2(pvj1.w, pvj1.z);
        }
        SUBBAR();

        // prefetch next iteration
        {
            int e0 = base + stride8 + sub * 2;
            pv0 = e0 < EE; pv1 = (e0 + 1) < EE;
            if (pv0) {
                int s0 = is64 ? ei[2 * e0] : ei[e0];
                pt0    = is64 ? ei[2 * (EE + e0)] : ei[EE + e0];
                pc0 = g_inv[pt0];
                pvi0 = *(const float4*)(hin + (size_t)pt0 * 512 + r0 * 64 + d0);
                pvj0 = *(const float4*)(hin + (size_t)s0  * 512 + r0 * 64 + d0);
            }
            if (pv1) {
                int e1 = e0 + 1;
                int s1 = is64 ? ei[2 * e1] : ei[e1];
                pt1    = is64 ? ei[2 * (EE + e1)] : ei[EE + e1];
                pc1 = g_inv[pt1];
                pvi1 = *(const float4*)(hin + (size_t)pt1 * 512 + r0 * 64 + d0);
                pvj1 = *(const float4*)(hin + (size_t)s1  * 512 + r0 * 64 + d0);
            }
        }

        // P1: bproj (both edges) -> XCH rows 8..15 (half only; f32 copy dead)
        if (v0) {
            unsigned a0[4][4], a1[4][4];
            load_ah(a0, XSH(0), lane);
            load_ah(a1, XSH(1), lane);
            gemm2h<0, true>(a0, a1, Wb, s_b + 640, warp * 16,
                            XCH(0) + 8 * 36, XCH(1) + 8 * 36, 36, lane);
            gemm2h<0, true>(a0, a1, Wb, s_b + 640, warp * 16 + 8,
                            XCH(0) + 8 * 36, XCH(1) + 8 * 36, 36, lane);
        }
        SUBBAR();

        // P2+P3 fused: warp computes ITS OWN head's q/k/v, then its attention.
        if (v0) {
            unsigned a0[4][4], a1[4][4];
            load_ah(a0, XCH(0), lane);
            load_ah(a1, XCH(1), lane);
            #pragma unroll
            for (int nt = 0; nt < 6; nt++) {
                int jb = (nt < 2) ? (warp * 16 + nt * 8)
                       : (nt < 4) ? (64 + warp * 16 + (nt - 2) * 8)
                                  : (128 + warp * 16 + (nt - 4) * 8);
                int col0 = jb + 2 * tg;
                float2 bb = *(const float2*)(s_b + col0);
                float d00 = bb.x, d01 = bb.y, d02 = bb.x, d03 = bb.y;
                float d10 = bb.x, d11 = bb.y, d12 = bb.x, d13 = bb.y;
                const unsigned* wr = Wq + (jb + g) * 36 + tg;
                unsigned b0[4], b1[4];
                #pragma unroll
                for (int kc = 0; kc < 4; kc++) { b0[kc] = wr[kc * 8]; b1[kc] = wr[kc * 8 + 4]; }
                #pragma unroll
                for (int kc = 0; kc < 4; kc++)
                    mma_f16(d00, d01, d02, d03, a0[kc][0], a0[kc][1], a0[kc][2], a0[kc][3], b0[kc], b1[kc]);
                #pragma unroll
                for (int kc = 0; kc < 4; kc++)
                    mma_f16(d10, d11, d12, d13, a1[kc][0], a1[kc][1], a1[kc][2], a1[kc][3], b0[kc], b1[kc]);
                if (jb < 128) {
                    QVH(0)[g * 68 + (jb >> 1) + tg]       = packh2(d01, d00);
                    QVH(0)[(g + 8) * 68 + (jb >> 1) + tg] = packh2(d03, d02);
                    QVH(1)[g * 68 + (jb >> 1) + tg]       = packh2(d11, d10);
                    QVH(1)[(g + 8) * 68 + (jb >> 1) + tg] = packh2(d13, d12);
                } else {
                    int dL = jb - 128 + 2 * tg;
                    __half* vp0 = (__half*)VPW(0);
                    __half* vp1 = (__half*)VPW(1);
                    vp0[dL * 24 + g]           = __float2half_rn(d00);
                    vp0[(dL + 1) * 24 + g]     = __float2half_rn(d01);
                    vp0[dL * 24 + g + 8]       = __float2half_rn(d02);
                    vp0[(dL + 1) * 24 + g + 8] = __float2half_rn(d03);
                    vp1[dL * 24 + g]           = __float2half_rn(d10);
                    vp1[(dL + 1) * 24 + g]     = __float2half_rn(d11);
                    vp1[dL * 24 + g + 8]       = __float2half_rn(d12);
                    vp1[(dL + 1) * 24 + g + 8] = __float2half_rn(d13);
                }
            }
            __syncwarp();

            // P3: attention, queries 0..7 only; output packed into AOHP rows 8e+g
            #pragma unroll
            for (int e = 0; e < 2; e++) {
                const unsigned* qb = QVH(e) + warp * 8;
                const unsigned* kb = QVH(e) + 32 + warp * 8;
                unsigned a0q = qb[g * 68 + tg],     a1q = qb[(g + 8) * 68 + tg];
                unsigned a2q = qb[g * 68 + tg + 4], a3q = qb[(g + 8) * 68 + tg + 4];
                float s00 = 0, s01 = 0, s02 = 0, s03 = 0;
                float s10 = 0, s11 = 0, s12 = 0, s13 = 0;
                mma_f16(s00, s01, s02, s03, a0q, a1q, a2q, a3q,
                        kb[g * 68 + tg], kb[g * 68 + tg + 4]);
                mma_f16(s10, s11, s12, s13, a0q, a1q, a2q, a3q,
                        kb[(g + 8) * 68 + tg], kb[(g + 8) * 68 + tg + 4]);
                // softmax for query rows 0..7 only (rows g); bottom rows dead
                s00 *= 0.25f; s01 *= 0.25f; s10 *= 0.25f; s11 *= 0.25f;
                float m0 = fmaxf(fmaxf(s00, s01), fmaxf(s10, s11));
                m0 = fmaxf(m0, __shfl_xor_sync(0xffffffffu, m0, 1));
                m0 = fmaxf(m0, __shfl_xor_sync(0xffffffffu, m0, 2));
                float e00 = __expf(s00 - m0), e01 = __expf(s01 - m0);
                float e10 = __expf(s10 - m0), e11 = __expf(s11 - m0);
                float t0 = (e00 + e01) + (e10 + e11);
                t0 += __shfl_xor_sync(0xffffffffu, t0, 1);
                t0 += __shfl_xor_sync(0xffffffffu, t0, 2);
                float r0s = 1.f / t0;
                unsigned ap0 = packh2(e01 * r0s, e00 * r0s);   // row g, keys 2tg..+1
                unsigned ap2 = packh2(e11 * r0s, e10 * r0s);   // row g, keys 8+2tg..+1
                const unsigned* vb = VPW(e) + warp * 192;
                #pragma unroll
                for (int jb2 = 0; jb2 < 2; jb2++) {
                    float c0 = 0, c1 = 0, c2 = 0, c3 = 0;
                    const unsigned* vr = vb + (jb2 * 8 + g) * 12 + tg;
                    mma_f16(c0, c1, c2, c3, ap0, 0u, ap2, 0u, vr[0], vr[4]);
                    AOHP[(8 * e + g) * 36 + warp * 8 + jb2 * 4 + tg] = packh2(c1, c0);
                }
            }
        }
        SUBBAR();

        // P4: out_proj + residual, packed rows (0-7 edge0, 8-15 edge1); LN1 partials
        float p4[2][4];
        if (v0) {
            unsigned a[4][4];
            load_ah(a, AOHP, lane);
            #pragma unroll
            for (int jt = 0; jt < 2; jt++) {
                int jb = warp * 16 + jt * 8;
                int col0 = jb + 2 * tg;
                float2 bb = *(const float2*)(s_b + 192 + col0);
                float d00 = bb.x, d01 = bb.y, d02 = bb.x, d03 = bb.y;
                const unsigned* wr = Wo + (jb + g) * 36 + tg;
                #pragma unroll
                for (int kc = 0; kc < 4; kc++)
                    mma_f16(d00, d01, d02, d03, a[kc][0], a[kc][1], a[kc][2], a[kc][3],
                            wr[kc * 8], wr[kc * 8 + 4]);
                float2 r0v = *(const float2*)(XCF(0) + g * 68 + col0);
                float2 r1v = *(const float2*)(XCF(1) + g * 68 + col0);
                p4[0][jt * 2 + 0] = d00 + r0v.x; p4[0][jt * 2 + 1] = d01 + r0v.y;
                p4[1][jt * 2 + 0] = d02 + r1v.x; p4[1][jt * 2 + 1] = d03 + r1v.y;
            }
            #pragma unroll
            for (int e = 0; e < 2; e++) {
                float sg = (p4[e][0] + p4[e][1]) + (p4[e][2] + p4[e][3]);
                float qg = p4[e][0]*p4[e][0] + p4[e][1]*p4[e][1] + p4[e][2]*p4[e][2] + p4[e][3]*p4[e][3];
                sg += __shfl_xor_sync(0xffffffffu, sg, 1); sg += __shfl_xor_sync(0xffffffffu, sg, 2);
                qg += __shfl_xor_sync(0xffffffffu, qg, 1); qg += __shfl_xor_sync(0xffffffffu, qg, 2);
                if (tg == 0) {
                    PPB[(g + 8 * e) * 8 + warp]     = sg;
                    PPB[(g + 8 * e) * 8 + 4 + warp] = qg;
                }
            }
        }
        SUBBAR();

        // LN1 finish: packed rows -> XLNH (half) + XLNF (f32 for P7 residual)
        if (v0) {
            #pragma unroll
            for (int e = 0; e < 2; e++) {
                int row = g + 8 * e;
                float4 sx = *(const float4*)(PPB + row * 8);
                float4 sq = *(const float4*)(PPB + row * 8 + 4);
                float mu  = ((sx.x + sx.y) + (sx.z + sx.w)) * 0.015625f;
                float ex2 = ((sq.x + sq.y) + (sq.z + sq.w)) * 0.015625f;
                float rstd = rsqrtf(ex2 - mu * mu + 1e-5f);
                #pragma unroll
                for (int jt = 0; jt < 2; jt++) {
                    int jb = warp * 16 + jt * 8;
                    int col0 = jb + 2 * tg;
                    float2 gg = *(const float2*)(s_b + 384 + col0);
                    float2 be = *(const float2*)(s_b + 448 + col0);
                    float o0 = (p4[e][jt * 2 + 0] - mu) * rstd * gg.x + be.x;
                    float o1 = (p4[e][jt * 2 + 1] - mu) * rstd * gg.y + be.y;
                    *(float2*)(XLNF + row * 68 + col0) = make_float2(o0, o1);
                    XLNH[row * 36 + (jb >> 1) + tg] = packh2(o1, o0);
                }
            }
        }
        SUBBAR();

        // P6: FF1 + relu, packed -> AOHP
        if (v0) {
            unsigned a[4][4];
            load_ah(a, XLNH, lane);
            #pragma unroll
            for (int jt = 0; jt < 2; jt++) {
                int jb = warp * 16 + jt * 8;
                int col0 = jb + 2 * tg;
                float2 bb = *(const float2*)(s_b + 256 + col0);
                float d00 = bb.x, d01 = bb.y, d02 = bb.x, d03 = bb.y;
                const unsigned* wr = W1p + (jb + g) * 36 + tg;
                #pragma unroll
                for (int kc = 0; kc < 4; kc++)
                    mma_f16(d00, d01, d02, d03, a[kc][0], a[kc][1], a[kc][2], a[kc][3],
                            wr[kc * 8], wr[kc * 8 + 4]);
                d00 = fmaxf(d00, 0.f); d01 = fmaxf(d01, 0.f);
                d02 = fmaxf(d02, 0.f); d03 = fmaxf(d03, 0.f);
                AOHP[g * 36 + (jb >> 1) + tg]       = packh2(d01, d00);
                AOHP[(g + 8) * 36 + (jb >> 1) + tg] = packh2(d03, d02);
            }
        }
        SUBBAR();

        // P7: FF2 + residual, packed; LN2 partials
        float p7[2][4];
        if (v0) {
            unsigned a[4][4];
            load_ah(a, AOHP, lane);
            #pragma unroll
            for (int jt = 0; jt < 2; jt++) {
                int jb = warp * 16 + jt * 8;
                int col0 = jb + 2 * tg;
                float2 bb = *(const float2*)(s_b + 320 + col0);
                float d00 = bb.x, d01 = bb.y, d02 = bb.x, d03 = bb.y;
                const unsigned* wr = W2p + (jb + g) * 36 + tg;
                #pragma unroll
                for (int kc = 0; kc < 4; kc++)
                    mma_f16(d00, d01, d02, d03, a[kc][0], a[kc][1], a[kc][2], a[kc][3],
                            wr[kc * 8], wr[kc * 8 + 4]);
                float2 r0v = *(const float2*)(XLNF + g * 68 + col0);
                float2 r1v = *(const float2*)(XLNF + (g + 8) * 68 + col0);
                p7[0][jt * 2 + 0] = d00 + r0v.x; p7[0][jt * 2 + 1] = d01 + r0v.y;
                p7[1][jt * 2 + 0] = d02 + r1v.x; p7[1][jt * 2 + 1] = d03 + r1v.y;
            }
            #pragma unroll
            for (int e = 0; e < 2; e++) {
                float sg = (p7[e][0] + p7[e][1]) + (p7[e][2] + p7[e][3]);
                float qg = p7[e][0]*p7[e][0] + p7[e][1]*p7[e][1] + p7[e][2]*p7[e][2] + p7[e][3]*p7[e][3];
                sg += __shfl_xor_sync(0xffffffffu, sg, 1); sg += __shfl_xor_sync(0xffffffffu, sg, 2);
                qg += __shfl_xor_sync(0xffffffffu, qg, 1); qg += __shfl_xor_sync(0xffffffffu, qg, 2);
                if (tg == 0) {
                    PPB[(g + 8 * e) * 8 + warp]     = sg;
                    PPB[(g + 8 * e) * 8 + 4 + warp] = qg;
                }
            }
        }
        SUBBAR();

        // LN2 finish + scaled vector-atomic scatter (token rows 0..7, per edge)
        #pragma unroll
        for (int e = 0; e < 2; e++) {
            bool ve = e ? v1 : v0;
            if (!ve) continue;
            int tgte = e ? t1i : t0i;
            float ice = e ? c1i : c0i;
            int row = g + 8 * e;
            float4 sx = *(const float4*)(PPB + row * 8);
            float4 sq = *(const float4*)(PPB + row * 8 + 4);
            float mu  = ((sx.x + sx.y) + (sx.z + sx.w)) * 0.015625f;
            float ex2 = ((sq.x + sq.y) + (sq.z + sq.w)) * 0.015625f;
            float rstd = rsqrtf(ex2 - mu * mu + 1e-5f);
            #pragma unroll
            for (int jt = 0; jt < 2; jt++) {
                int col0 = warp * 16 + jt * 8 + 2 * tg;
                float2 gg = *(const float2*)(s_b + 512 + col0);
                float2 be = *(const float2*)(s_b + 576 + col0);
                float o0 = ((p7[e][jt * 2 + 0] - mu) * rstd * gg.x + be.x) * ice;
                float o1 = ((p7[e][jt * 2 + 1] - mu) * rstd * gg.y + be.y) * ice;
                float* dst = hout + (size_t)tgte * 512 + g * 64 + col0;
                asm volatile("red.global.add.v2.f32 [%0], {%1,%2};"
                             :: "l"(dst), "f"(o0), "f"(o1) : "memory");
            }
        }
        // no trailing barrier: LN2 reads PPB (next written at P4, barriers away);
        // next P0 writes XSH/XCH/XCF rows 0..7, last read at P4/P2 (behind barriers).
    }
}

__global__ void out_kernel(const float* __restrict__ ow, const float* __restrict__ ob,
                           float* __restrict__ out) {
    __shared__ float shs[8][64];
    int w = threadIdx.x >> 5, lane = threadIdx.x & 31;
    int n = blockIdx.x * 8 + w;
    if (n >= NN) return;
    const float* hr = g_hA + (size_t)n * 512;
    float lo = 0.f, hi = 0.f;
    #pragma unroll
    for (int c = 0; c < 8; c++) { lo += hr[c * 64 + lane]; hi += hr[c * 64 + 32 + lane]; }
    shs[w][lane] = lo; shs[w][lane + 32] = hi;
    __syncwarp();
    float z = -1e30f;
    if (lane < 16) {
        float acc = 8.f * ob[lane];
        const float* wr = ow + lane * 64;
        #pragma unroll
        for (int d = 0; d < 64; d++) acc = fmaf(shs[w][d], wr[d], acc);
        z = acc;
    }
    float m = z;
    #pragma unroll
    for (int off = 8; off; off >>= 1) m = fmaxf(m, __shfl_xor_sync(0xffffffffu, m, off, 16));
    float p = __expf(z - m);
    float s = p;
    #pragma unroll
    for (int off = 8; off; off >>= 1) s += __shfl_xor_sync(0xffffffffu, s, off, 16);
    if (lane < 16) out[n * 16 + lane] = p / s;
}

extern "C" void kernel_launch(void* const* d_in, const int* in_sizes, int n_in,
                              void* d_out, int out_size) {
    const float* x    = (const float*)d_in[0];
    const int*   ei   = (const int*)d_in[1];
    const float* numw = (const float*)d_in[2];
    const float* numb = (const float*)d_in[3];
    const float* bpw  = (const float*)d_in[4];
    const float* bpb  = (const float*)d_in[5];
    const float* ipw  = (const float*)d_in[6];
    const float* ipb  = (const float*)d_in[7];
    const float* opw  = (const float*)d_in[8];
    const float* opb  = (const float*)d_in[9];
    const float* g1   = (const float*)d_in[10];
    const float* b1   = (const float*)d_in[11];
    const float* g2   = (const float*)d_in[12];
    const float* b2   = (const float*)d_in[13];
    const float* w1   = (const float*)d_in[14];
    const float* fb1  = (const float*)d_in[15];
    const float* w2   = (const float*)d_in[16];
    const float* fb2  = (const float*)d_in[17];
    const float* ow   = (const float*)d_in[18];
    const float* ob   = (const float*)d_in[19];
    float* out = (float*)d_out;

    const int SMEM_BYTES = SMEM_WORDS * 4;
    cudaFuncSetAttribute(edge_kernel, cudaFuncAttributeMaxDynamicSharedMemorySize, SMEM_BYTES);

    int dev = 0, sms = 148;
    cudaGetDevice(&dev);
    cudaDeviceGetAttribute(&sms, cudaDevAttrMultiProcessorCount, dev);

    setup0_kernel<<<(NN * 128 + 255) / 256, 256>>>();
    detect_kernel<<<256, 256>>>(ei);
    embed_kernel<<<(NN * 512 + 255) / 256, 256>>>(x, numw, numb);
    count_kernel<<<(EE + 255) / 256, 256>>>(ei);
    fin_cnt_kernel<<<(NN + 255) / 256, 256>>>();

    edge_kernel<<<sms, 512, SMEM_BYTES>>>(ei, 0,
        bpw, bpb, ipw, ipb, opw, opb, g1, b1, g2, b2, w1, fb1, w2, fb2);

    zeroA_kernel<<<(NN * 128 + 255) / 256, 256>>>();
    edge_kernel<<<sms, 512, SMEM_BYTES>>>(ei, 1,
        bpw + 64 * 64, bpb + 64, ipw + 192 * 64, ipb + 192, opw + 64 * 64, opb + 64,
        g1 + 64, b1 + 64, g2 + 64, b2 + 64,
        w1 + 64 * 64, fb1 + 64, w2 + 64 * 64, fb2 + 64);

    out_kernel<<<(NN + 7) / 8, 256>>>(ow, ob, out);
}